// round 7
// baseline (speedup 1.0000x reference)
#include <cuda_runtime.h>
#include <cuda_bf16.h>
#include <cstdint>

// Problem constants
#define BB 8
#define LL 1024
#define DD 768
#define HH 12
#define DHH 64
#define MM (BB*LL)   // 8192
#define LOG2E 1.4426950408889634f
#define S512 512.0f
#define I512 0.001953125f

// ---------------------------------------------------------------------------
// Scratch (device globals — no allocation allowed)
// ---------------------------------------------------------------------------
// attention operands: bf16 hi/lo [B,H,L,Dh]
__device__ __nv_bfloat16 g_qh[BB*HH*LL*DHH], g_ql[BB*HH*LL*DHH];
__device__ __nv_bfloat16 g_kh[BB*HH*LL*DHH], g_kl[BB*HH*LL*DHH];
__device__ __nv_bfloat16 g_vh[BB*HH*LL*DHH], g_vl[BB*HH*LL*DHH];
// GEMM operand encodings: hi bf16 + e4m3(lo*512) + e5m2(hi/512)
__device__ __nv_bfloat16 g_xh[3][MM*DD];
__device__ uint8_t       g_xc[3][MM*DD], g_xd[3][MM*DD];
__device__ __nv_bfloat16 g_wh[4][DD*DD];
__device__ uint8_t       g_wc[4][DD*DD], g_wd[4][DD*DD];
__device__ __nv_bfloat16 g_ch[MM*DD];
__device__ uint8_t       g_cc[MM*DD], g_cd[MM*DD];
// bit-packed mask + per-tile flags
__device__ uint32_t g_mbits[BB*LL*(LL/32)];
__device__ unsigned char g_mflags[BB*8*8];

// ---------------------------------------------------------------------------
// PTX helpers — baseline (non-'a') features only
// ---------------------------------------------------------------------------
__device__ __forceinline__ uint32_t smem_u32(const void* p) {
    uint32_t a;
    asm("{ .reg .u64 t; cvta.to.shared.u64 t, %1; cvt.u32.u64 %0, t; }"
        : "=r"(a) : "l"(p));
    return a;
}
__device__ __forceinline__ void cp_async16(uint32_t saddr, const void* gptr) {
    asm volatile("cp.async.cg.shared.global [%0], [%1], 16;"
                 :: "r"(saddr), "l"(gptr) : "memory");
}
__device__ __forceinline__ void cp_commit() {
    asm volatile("cp.async.commit_group;" ::: "memory");
}
template<int N>
__device__ __forceinline__ void cp_wait() {
    asm volatile("cp.async.wait_group %0;" :: "n"(N) : "memory");
}
__device__ __forceinline__ void ldmatrix_x4(uint32_t& r0, uint32_t& r1,
                                            uint32_t& r2, uint32_t& r3,
                                            uint32_t addr) {
    asm volatile("ldmatrix.sync.aligned.m8n8.x4.shared.b16 {%0,%1,%2,%3}, [%4];"
                 : "=r"(r0), "=r"(r1), "=r"(r2), "=r"(r3) : "r"(addr));
}
__device__ __forceinline__ void ldmatrix_x4_t(uint32_t& r0, uint32_t& r1,
                                              uint32_t& r2, uint32_t& r3,
                                              uint32_t addr) {
    asm volatile("ldmatrix.sync.aligned.m8n8.x4.trans.shared.b16 {%0,%1,%2,%3}, [%4];"
                 : "=r"(r0), "=r"(r1), "=r"(r2), "=r"(r3) : "r"(addr));
}
__device__ __forceinline__ void mma_bf16(float* c, const uint32_t* a,
                                         uint32_t b0, uint32_t b1) {
    asm volatile(
        "mma.sync.aligned.m16n8k16.row.col.f32.bf16.bf16.f32 "
        "{%0,%1,%2,%3}, {%4,%5,%6,%7}, {%8,%9}, {%0,%1,%2,%3};"
        : "+f"(c[0]), "+f"(c[1]), "+f"(c[2]), "+f"(c[3])
        : "r"(a[0]), "r"(a[1]), "r"(a[2]), "r"(a[3]), "r"(b0), "r"(b1));
}
// fp8 k32 MMAs: A=e4m3, B=e5m2 and A=e5m2, B=e4m3
__device__ __forceinline__ void mma_e4e5(float* c, const uint32_t* a,
                                         uint32_t b0, uint32_t b1) {
    asm volatile(
        "mma.sync.aligned.m16n8k32.row.col.f32.e4m3.e5m2.f32 "
        "{%0,%1,%2,%3}, {%4,%5,%6,%7}, {%8,%9}, {%0,%1,%2,%3};"
        : "+f"(c[0]), "+f"(c[1]), "+f"(c[2]), "+f"(c[3])
        : "r"(a[0]), "r"(a[1]), "r"(a[2]), "r"(a[3]), "r"(b0), "r"(b1));
}
__device__ __forceinline__ void mma_e5e4(float* c, const uint32_t* a,
                                         uint32_t b0, uint32_t b1) {
    asm volatile(
        "mma.sync.aligned.m16n8k32.row.col.f32.e5m2.e4m3.f32 "
        "{%0,%1,%2,%3}, {%4,%5,%6,%7}, {%8,%9}, {%0,%1,%2,%3};"
        : "+f"(c[0]), "+f"(c[1]), "+f"(c[2]), "+f"(c[3])
        : "r"(a[0]), "r"(a[1]), "r"(a[2]), "r"(a[3]), "r"(b0), "r"(b1));
}
__device__ __forceinline__ void split2(float v0, float v1,
                                       uint32_t& hi, uint32_t& lo) {
    __nv_bfloat162 h = __floats2bfloat162_rn(v0, v1);
    hi = *reinterpret_cast<uint32_t*>(&h);
    float2 hf = __bfloat1622float2(h);
    __nv_bfloat162 l = __floats2bfloat162_rn(v0 - hf.x, v1 - hf.y);
    lo = *reinterpret_cast<uint32_t*>(&l);
}
__device__ __forceinline__ uint16_t cvt_e4m3x2(float lo, float hi) {
    uint16_t r;
    asm("cvt.rn.satfinite.e4m3x2.f32 %0, %2, %1;" : "=h"(r) : "f"(lo), "f"(hi));
    return r;
}
__device__ __forceinline__ uint16_t cvt_e5m2x2(float lo, float hi) {
    uint16_t r;
    asm("cvt.rn.satfinite.e5m2x2.f32 %0, %2, %1;" : "=h"(r) : "f"(lo), "f"(hi));
    return r;
}

// ---------------------------------------------------------------------------
// Mask preprocessing
// ---------------------------------------------------------------------------
__global__ __launch_bounds__(256)
void pack_mask(const unsigned char* __restrict__ mask)
{
    int i = blockIdx.x * blockDim.x + threadIdx.x;
    const uint4* p = reinterpret_cast<const uint4*>(mask + (size_t)i * 32);
    uint4 u0 = p[0], u1 = p[1];
    uint32_t ws[8] = {u0.x, u0.y, u0.z, u0.w, u1.x, u1.y, u1.z, u1.w};
    uint32_t r = 0;
    #pragma unroll
    for (int w = 0; w < 8; w++)
        #pragma unroll
        for (int k = 0; k < 4; k++)
            if ((ws[w] >> (8 * k)) & 0xFFu) r |= 1u << (w * 4 + k);
    g_mbits[i] = r;
}

__global__ __launch_bounds__(128)
void mask_flags()
{
    int kt = blockIdx.x, qt = blockIdx.y, b = blockIdx.z;
    int row = qt * 128 + threadIdx.x;
    const uint32_t* p = g_mbits + ((size_t)(b * LL + row)) * (LL / 32) + kt * 4;
    uint32_t v = p[0] | p[1] | p[2] | p[3];
    int any = __syncthreads_or(v != 0);
    if (threadIdx.x == 0) g_mflags[(b * 8 + qt) * 8 + kt] = (unsigned char)any;
}

// ---------------------------------------------------------------------------
// Splits: x -> (hi bf16, e4m3(lo*512), e5m2(hi/512))
// ---------------------------------------------------------------------------
__device__ __forceinline__ void split_hcd(const float* src, __nv_bfloat16* H,
                                          uint8_t* C, uint8_t* D, int i)
{
    float4 f = reinterpret_cast<const float4*>(src)[i];
    __nv_bfloat162 h0 = __floats2bfloat162_rn(f.x, f.y);
    __nv_bfloat162 h1 = __floats2bfloat162_rn(f.z, f.w);
    float2 a0 = __bfloat1622float2(h0);
    float2 a1 = __bfloat1622float2(h1);
    uint32_t c32 = (uint32_t)cvt_e4m3x2((f.x - a0.x) * S512, (f.y - a0.y) * S512)
                 | ((uint32_t)cvt_e4m3x2((f.z - a1.x) * S512, (f.w - a1.y) * S512) << 16);
    uint32_t d32 = (uint32_t)cvt_e5m2x2(a0.x * I512, a0.y * I512)
                 | ((uint32_t)cvt_e5m2x2(a1.x * I512, a1.y * I512) << 16);
    uint32_t* hp = reinterpret_cast<uint32_t*>(H);
    hp[2*i]   = *reinterpret_cast<uint32_t*>(&h0);
    hp[2*i+1] = *reinterpret_cast<uint32_t*>(&h1);
    reinterpret_cast<uint32_t*>(C)[i] = c32;
    reinterpret_cast<uint32_t*>(D)[i] = d32;
}

__global__ __launch_bounds__(256)
void split_x(const float* __restrict__ q, const float* __restrict__ k,
             const float* __restrict__ v)
{
    int z = blockIdx.z;
    const float* src = (z == 0) ? q : (z == 1) ? k : v;
    split_hcd(src, g_xh[z], g_xc[z], g_xd[z],
              blockIdx.x * blockDim.x + threadIdx.x);
}

__global__ __launch_bounds__(256)
void split_w(const float* __restrict__ w0, const float* __restrict__ w1,
             const float* __restrict__ w2, const float* __restrict__ w3)
{
    int z = blockIdx.z;
    const float* src = (z == 0) ? w0 : (z == 1) ? w1 : (z == 2) ? w2 : w3;
    split_hcd(src, g_wh[z], g_wc[z], g_wd[z],
              blockIdx.x * blockDim.x + threadIdx.x);
}

// ---------------------------------------------------------------------------
// GEMM core: C = Ah·Bh (bf16 k16) + Ac·Bd + Ad·Bc (fp8 k32), all into fp32 acc.
// Block 128x128, BK=32, 8 warps.
// ---------------------------------------------------------------------------
#define PH      80                       // bf16 tile pitch (64B data + pad)
#define PF      48                       // fp8 tile pitch (32B data + pad)
#define AH_OFF  0
#define BH_OFF  10240
#define AC_OFF  20480
#define AD_OFF  26624
#define BC_OFF  32768
#define BD_OFF  38912
#define STAGE_B 45056
#define NCHUNK  (DD / 32)                // 24

__device__ __forceinline__ void gemm_core(
    const __nv_bfloat16* __restrict__ Ah, const uint8_t* __restrict__ Ac,
    const uint8_t* __restrict__ Ad,
    const __nv_bfloat16* __restrict__ Bh, const uint8_t* __restrict__ Bc,
    const uint8_t* __restrict__ Bd,
    uint32_t sbase, int tid, float acc[2][8][4])
{
    const int wid = tid >> 5, lane = tid & 31;
    const int wm = wid & 3, wn = wid >> 2;

    // per-thread load slot: 16 segments per row-group of 16 rows
    const int s16  = tid & 15;
    const int row0 = tid >> 4;
    const char* gB; uint32_t soffb; int spitch, gpitch, gmul;
    if (s16 < 4)       { gB=(const char*)Ah + s16*16;      soffb=AH_OFF+s16*16;      spitch=PH; gpitch=1536; gmul=2; }
    else if (s16 < 8)  { gB=(const char*)Bh + (s16-4)*16;  soffb=BH_OFF+(s16-4)*16;  spitch=PH; gpitch=1536; gmul=2; }
    else if (s16 < 10) { gB=(const char*)Ac + (s16-8)*16;  soffb=AC_OFF+(s16-8)*16;  spitch=PF; gpitch=768;  gmul=1; }
    else if (s16 < 12) { gB=(const char*)Ad + (s16-10)*16; soffb=AD_OFF+(s16-10)*16; spitch=PF; gpitch=768;  gmul=1; }
    else if (s16 < 14) { gB=(const char*)Bc + (s16-12)*16; soffb=BC_OFF+(s16-12)*16; spitch=PF; gpitch=768;  gmul=1; }
    else               { gB=(const char*)Bd + (s16-14)*16; soffb=BD_OFF+(s16-14)*16; spitch=PF; gpitch=768;  gmul=1; }

    auto load_chunk = [&](int kc, int st) {
        const char* g = gB + kc * 32 * gmul;
        uint32_t s = sbase + st * STAGE_B + soffb;
        #pragma unroll
        for (int t = 0; t < 8; t++) {
            int row = row0 + t * 16;
            cp_async16(s + row * spitch, g + (size_t)row * gpitch);
        }
        cp_commit();
    };

    load_chunk(0, 0);

    const int lrow = lane & 15;
    const int lhalf = lane >> 4;

    #pragma unroll 1
    for (int c = 0; c < NCHUNK; c++) {
        const int s = c & 1;
        if (c + 1 < NCHUNK) { load_chunk(c + 1, s ^ 1); cp_wait<1>(); }
        else                { cp_wait<0>(); }
        __syncthreads();

        const uint32_t stg = sbase + s * STAGE_B;

        // ---- hi x hi, bf16 k16 x2 ----
        #pragma unroll
        for (int ks = 0; ks < 2; ks++) {
            const int seg = ks * 2 + lhalf;
            uint32_t ah[2][4];
            #pragma unroll
            for (int mf = 0; mf < 2; mf++) {
                uint32_t off = (uint32_t)((wm * 32 + mf * 16 + lrow) * PH + seg * 16);
                ldmatrix_x4(ah[mf][0], ah[mf][1], ah[mf][2], ah[mf][3],
                            stg + AH_OFF + off);
            }
            #pragma unroll
            for (int ng = 0; ng < 4; ng++) {
                uint32_t off = (uint32_t)((wn * 64 + ng * 16 + lrow) * PH + seg * 16);
                uint32_t b0, b1, b2, b3;
                ldmatrix_x4(b0, b1, b2, b3, stg + BH_OFF + off);
                #pragma unroll
                for (int mf = 0; mf < 2; mf++) {
                    mma_bf16(acc[mf][2*ng  ], ah[mf], b0, b2);
                    mma_bf16(acc[mf][2*ng+1], ah[mf], b1, b3);
                }
            }
        }

        // ---- cross terms, fp8 k32 ----
        {
            uint32_t acr[2][4], adr[2][4];
            #pragma unroll
            for (int mf = 0; mf < 2; mf++) {
                uint32_t off = (uint32_t)((wm * 32 + mf * 16 + lrow) * PF + lhalf * 16);
                ldmatrix_x4(acr[mf][0], acr[mf][1], acr[mf][2], acr[mf][3],
                            stg + AC_OFF + off);
                ldmatrix_x4(adr[mf][0], adr[mf][1], adr[mf][2], adr[mf][3],
                            stg + AD_OFF + off);
            }
            #pragma unroll
            for (int ng = 0; ng < 4; ng++) {
                uint32_t off = (uint32_t)((wn * 64 + ng * 16 + lrow) * PF + lhalf * 16);
                uint32_t d0, d1, d2, d3, c0, c1, c2, c3;
                ldmatrix_x4(d0, d1, d2, d3, stg + BD_OFF + off);
                ldmatrix_x4(c0, c1, c2, c3, stg + BC_OFF + off);
                #pragma unroll
                for (int mf = 0; mf < 2; mf++) {
                    mma_e4e5(acc[mf][2*ng  ], acr[mf], d0, d2);   // Al*Bh
                    mma_e4e5(acc[mf][2*ng+1], acr[mf], d1, d3);
                    mma_e5e4(acc[mf][2*ng  ], adr[mf], c0, c2);   // Ah*Bl
                    mma_e5e4(acc[mf][2*ng+1], adr[mf], c1, c3);
                }
            }
        }
        __syncthreads();
    }
}

// Fused Q/K/V projection GEMMs -> bf16 hi/lo scattered [B,H,L,Dh].
__global__ __launch_bounds__(256, 2)
void qkv_gemm(const float* __restrict__ bq, const float* __restrict__ bk,
              const float* __restrict__ bv)
{
    extern __shared__ __align__(128) char smem[];
    const int z = blockIdx.z;
    const int m0 = blockIdx.y * 128, n0 = blockIdx.x * 128;
    const int tid = threadIdx.x;
    const int wid = tid >> 5, lane = tid & 31;
    const int wm = wid & 3, wn = wid >> 2;

    const float* bias = (z == 0) ? bq : (z == 1) ? bk : bv;
    __nv_bfloat16* oh = (z == 0) ? g_qh : (z == 1) ? g_kh : g_vh;
    __nv_bfloat16* ol = (z == 0) ? g_ql : (z == 1) ? g_kl : g_vl;
    const float scale = (z == 0) ? 0.125f * LOG2E : 1.0f;

    float acc[2][8][4];
    #pragma unroll
    for (int i = 0; i < 2; i++)
        #pragma unroll
        for (int j = 0; j < 8; j++)
            #pragma unroll
            for (int k = 0; k < 4; k++) acc[i][j][k] = 0.f;

    gemm_core(g_xh[z] + (size_t)m0 * DD, g_xc[z] + (size_t)m0 * DD,
              g_xd[z] + (size_t)m0 * DD,
              g_wh[z] + (size_t)n0 * DD, g_wc[z] + (size_t)n0 * DD,
              g_wd[z] + (size_t)n0 * DD,
              smem_u32(smem), tid, acc);

    #pragma unroll
    for (int nf = 0; nf < 8; nf++) {
        const int col = n0 + wn * 64 + nf * 8 + (lane & 3) * 2;
        const float b0 = bias[col], b1 = bias[col + 1];
        #pragma unroll
        for (int mf = 0; mf < 2; mf++) {
            const int r0 = m0 + wm * 32 + mf * 16 + (lane >> 2);
            const float* a = acc[mf][nf];
            #pragma unroll
            for (int half = 0; half < 2; half++) {
                const int m = r0 + half * 8;
                float v0 = (a[2*half] + b0) * scale, v1 = (a[2*half+1] + b1) * scale;
                uint32_t hp, lp;
                split2(v0, v1, hp, lp);
                int bb = m >> 10, l = m & 1023;
                int hh = col >> 6, d = col & 63;
                size_t idx = (((size_t)(bb * HH + hh) << 10) + l) * DHH + d;
                *reinterpret_cast<uint32_t*>(oh + idx) = hp;
                *reinterpret_cast<uint32_t*>(ol + idx) = lp;
            }
        }
    }
}

// Output projection GEMM -> fp32 d_out.
__global__ __launch_bounds__(256, 2)
void out_gemm(const float* __restrict__ bias, float* __restrict__ out)
{
    extern __shared__ __align__(128) char smem[];
    const int m0 = blockIdx.y * 128, n0 = blockIdx.x * 128;
    const int tid = threadIdx.x;
    const int wid = tid >> 5, lane = tid & 31;
    const int wm = wid & 3, wn = wid >> 2;

    float acc[2][8][4];
    #pragma unroll
    for (int i = 0; i < 2; i++)
        #pragma unroll
        for (int j = 0; j < 8; j++)
            #pragma unroll
            for (int k = 0; k < 4; k++) acc[i][j][k] = 0.f;

    gemm_core(g_ch + (size_t)m0 * DD, g_cc + (size_t)m0 * DD,
              g_cd + (size_t)m0 * DD,
              g_wh[3] + (size_t)n0 * DD, g_wc[3] + (size_t)n0 * DD,
              g_wd[3] + (size_t)n0 * DD,
              smem_u32(smem), tid, acc);

    #pragma unroll
    for (int nf = 0; nf < 8; nf++) {
        const int col = n0 + wn * 64 + nf * 8 + (lane & 3) * 2;
        const float b0 = bias[col], b1 = bias[col + 1];
        #pragma unroll
        for (int mf = 0; mf < 2; mf++) {
            const int r0 = m0 + wm * 32 + mf * 16 + (lane >> 2);
            const float* a = acc[mf][nf];
            #pragma unroll
            for (int half = 0; half < 2; half++) {
                const int m = r0 + half * 8;
                *reinterpret_cast<float2*>(out + (size_t)m * DD + col)
                    = make_float2(a[2*half] + b0, a[2*half+1] + b1);
            }
        }
    }
}

// ---------------------------------------------------------------------------
// HMMA flash attention (unchanged mainloop; epilogue emits h/c/d for out_gemm)
// ---------------------------------------------------------------------------
#define AROWB   144
#define ATILE_B (128 * AROWB)
#define KVSTG_B (4 * ATILE_B)
#define ASMEM   (2 * ATILE_B + 2 * KVSTG_B)

__global__ __launch_bounds__(256, 1)
void attn_mma()
{
    extern __shared__ __align__(128) char smem[];
    const uint32_t sb = smem_u32(smem);
    const int tid = threadIdx.x, wid = tid >> 5, lane = tid & 31;
    const int qt = blockIdx.x, h = blockIdx.y, b = blockIdx.z;
    const int q0 = qt * 128;
    const size_t hb = ((size_t)(b * HH + h)) << 16;

    const uint32_t SQH = sb, SQL = sb + ATILE_B;
    auto stage = [&](int s) { return sb + 2 * ATILE_B + (uint32_t)s * KVSTG_B; };

    auto load_tile = [&](const __nv_bfloat16* g, uint32_t s) {
        #pragma unroll
        for (int it = 0; it < 4; it++) {
            int id = tid + it * 256;
            int row = id >> 3, seg = id & 7;
            cp_async16(s + row * AROWB + seg * 16, g + (size_t)row * 64 + seg * 8);
        }
    };
    auto load_kv = [&](int t, int s) {
        const size_t off = hb + (size_t)t * 128 * 64;
        uint32_t st = stage(s);
        load_tile(g_kh + off, st);
        load_tile(g_kl + off, st + ATILE_B);
        load_tile(g_vh + off, st + 2 * ATILE_B);
        load_tile(g_vl + off, st + 3 * ATILE_B);
        cp_commit();
    };

    load_tile(g_qh + hb + (size_t)q0 * 64, SQH);
    load_tile(g_ql + hb + (size_t)q0 * 64, SQL);
    cp_commit();
    load_kv(0, 0);
    cp_wait<1>();
    __syncthreads();

    const int lr = lane & 15, lh = lane >> 4;
    uint32_t qfh[4][4], qfl[4][4];
    #pragma unroll
    for (int ks = 0; ks < 4; ks++) {
        uint32_t off = (uint32_t)((wid * 16 + lr) * AROWB + ks * 32 + lh * 16);
        ldmatrix_x4(qfh[ks][0], qfh[ks][1], qfh[ks][2], qfh[ks][3], SQH + off);
        ldmatrix_x4(qfl[ks][0], qfl[ks][1], qfl[ks][2], qfl[ks][3], SQL + off);
    }

    float mA = -INFINITY, mB = -INFINITY, lA = 0.f, lB = 0.f;
    float o[8][4];
    #pragma unroll
    for (int i = 0; i < 8; i++)
        #pragma unroll
        for (int j = 0; j < 4; j++) o[i][j] = 0.f;

    const unsigned char* flagp = g_mflags + (b * 8 + qt) * 8;

    #pragma unroll 1
    for (int t = 0; t < 8; t++) {
        if (t < 7) { load_kv(t + 1, (t + 1) & 1); cp_wait<1>(); }
        else       { cp_wait<0>(); }
        __syncthreads();
        const uint32_t st = stage(t & 1);

        float s[16][4];
        #pragma unroll
        for (int j = 0; j < 16; j++)
            #pragma unroll
            for (int k = 0; k < 4; k++) s[j][k] = 0.f;

        #pragma unroll
        for (int ks = 0; ks < 4; ks++) {
            #pragma unroll
            for (int ng = 0; ng < 8; ng++) {
                uint32_t off = (uint32_t)((ng * 16 + lr) * AROWB + ks * 32 + lh * 16);
                uint32_t k0, k1, k2, k3, l0, l1, l2, l3;
                ldmatrix_x4(k0, k1, k2, k3, st + off);
                ldmatrix_x4(l0, l1, l2, l3, st + ATILE_B + off);
                mma_bf16(s[2*ng  ], qfh[ks], k0, k2);
                mma_bf16(s[2*ng+1], qfh[ks], k1, k3);
                mma_bf16(s[2*ng  ], qfh[ks], l0, l2);
                mma_bf16(s[2*ng+1], qfh[ks], l1, l3);
                mma_bf16(s[2*ng  ], qfl[ks], k0, k2);
                mma_bf16(s[2*ng+1], qfl[ks], k1, k3);
            }
        }

        if (flagp[t]) {
            const uint32_t* mr = g_mbits
                + ((size_t)(b * LL + q0 + wid * 16 + (lane >> 2))) * (LL / 32) + t * 4;
            uint32_t wA[4], wB[4];
            #pragma unroll
            for (int ww = 0; ww < 4; ww++) { wA[ww] = mr[ww]; wB[ww] = mr[8 * (LL/32) + ww]; }
            #pragma unroll
            for (int j = 0; j < 16; j++) {
                int bp = (j & 3) * 8 + (lane & 3) * 2;
                uint32_t a = wA[j >> 2], bw = wB[j >> 2];
                if ((a  >> bp)      & 1u) s[j][0] = -INFINITY;
                if ((a  >> (bp+1))  & 1u) s[j][1] = -INFINITY;
                if ((bw >> bp)      & 1u) s[j][2] = -INFINITY;
                if ((bw >> (bp+1))  & 1u) s[j][3] = -INFINITY;
            }
        }

        float mxA = -INFINITY, mxB = -INFINITY;
        #pragma unroll
        for (int j = 0; j < 16; j++) {
            mxA = fmaxf(mxA, fmaxf(s[j][0], s[j][1]));
            mxB = fmaxf(mxB, fmaxf(s[j][2], s[j][3]));
        }
        mxA = fmaxf(mxA, __shfl_xor_sync(0xffffffffu, mxA, 1));
        mxA = fmaxf(mxA, __shfl_xor_sync(0xffffffffu, mxA, 2));
        mxB = fmaxf(mxB, __shfl_xor_sync(0xffffffffu, mxB, 1));
        mxB = fmaxf(mxB, __shfl_xor_sync(0xffffffffu, mxB, 2));
        float mnA = fmaxf(mA, mxA), mnB = fmaxf(mB, mxB);
        float aA = (mA == -INFINITY) ? 0.f : exp2f(mA - mnA);
        float aB = (mB == -INFINITY) ? 0.f : exp2f(mB - mnB);
        float subA = (mnA == -INFINITY) ? 0.f : mnA;
        float subB = (mnB == -INFINITY) ? 0.f : mnB;
        float sA = 0.f, sB = 0.f;
        #pragma unroll
        for (int j = 0; j < 16; j++) {
            s[j][0] = exp2f(s[j][0] - subA);
            s[j][1] = exp2f(s[j][1] - subA);
            s[j][2] = exp2f(s[j][2] - subB);
            s[j][3] = exp2f(s[j][3] - subB);
            sA += s[j][0] + s[j][1];
            sB += s[j][2] + s[j][3];
        }
        sA += __shfl_xor_sync(0xffffffffu, sA, 1);
        sA += __shfl_xor_sync(0xffffffffu, sA, 2);
        sB += __shfl_xor_sync(0xffffffffu, sB, 1);
        sB += __shfl_xor_sync(0xffffffffu, sB, 2);
        lA = lA * aA + sA; lB = lB * aB + sB;
        mA = mnA; mB = mnB;
        #pragma unroll
        for (int nf = 0; nf < 8; nf++) {
            o[nf][0] *= aA; o[nf][1] *= aA;
            o[nf][2] *= aB; o[nf][3] *= aB;
        }

        #pragma unroll
        for (int ks = 0; ks < 8; ks++) {
            uint32_t aph[4], apl[4];
            split2(s[2*ks  ][0], s[2*ks  ][1], aph[0], apl[0]);
            split2(s[2*ks  ][2], s[2*ks  ][3], aph[1], apl[1]);
            split2(s[2*ks+1][0], s[2*ks+1][1], aph[2], apl[2]);
            split2(s[2*ks+1][2], s[2*ks+1][3], aph[3], apl[3]);
            #pragma unroll
            for (int ng = 0; ng < 4; ng++) {
                uint32_t voff = (uint32_t)((ks * 16 + lr) * AROWB + ng * 32 + lh * 16);
                uint32_t v0, v1, v2, v3, w0, w1, w2, w3;
                ldmatrix_x4_t(v0, v1, v2, v3, st + 2 * ATILE_B + voff);
                ldmatrix_x4_t(w0, w1, w2, w3, st + 3 * ATILE_B + voff);
                mma_bf16(o[2*ng  ], aph, v0, v1);
                mma_bf16(o[2*ng+1], aph, v2, v3);
                mma_bf16(o[2*ng  ], aph, w0, w1);
                mma_bf16(o[2*ng+1], aph, w2, w3);
                mma_bf16(o[2*ng  ], apl, v0, v1);
                mma_bf16(o[2*ng+1], apl, v2, v3);
            }
        }
        __syncthreads();
    }

    // ---- epilogue: write ctx as (hi bf16, e4m3(lo*512), e5m2(hi/512)) ----
    float iA = (lA > 0.f) ? (1.f / lA) : 0.f;
    float iB = (lB > 0.f) ? (1.f / lB) : 0.f;
    size_t rowA = (size_t)b * LL + q0 + wid * 16 + (lane >> 2);
    size_t rowB = rowA + 8;
    #pragma unroll
    for (int nf = 0; nf < 8; nf++) {
        int col = h * 64 + nf * 8 + (lane & 3) * 2;
        #pragma unroll
        for (int half = 0; half < 2; half++) {
            size_t row = half ? rowB : rowA;
            float v0 = o[nf][2*half]   * (half ? iB : iA);
            float v1 = o[nf][2*half+1] * (half ? iB : iA);
            __nv_bfloat162 h2 = __floats2bfloat162_rn(v0, v1);
            float2 hf = __bfloat1622float2(h2);
            size_t idx = row * DD + col;
            *reinterpret_cast<uint32_t*>(g_ch + idx) = *reinterpret_cast<uint32_t*>(&h2);
            *reinterpret_cast<uint16_t*>(g_cc + idx) =
                cvt_e4m3x2((v0 - hf.x) * S512, (v1 - hf.y) * S512);
            *reinterpret_cast<uint16_t*>(g_cd + idx) =
                cvt_e5m2x2(hf.x * I512, hf.y * I512);
        }
    }
}

// ---------------------------------------------------------------------------
extern "C" void kernel_launch(void* const* d_in, const int* in_sizes, int n_in,
                              void* d_out, int out_size)
{
    const float* Query = (const float*)d_in[0];
    const float* Key   = (const float*)d_in[1];
    const float* Value = (const float*)d_in[2];
    const unsigned char* maskp = (const unsigned char*)d_in[3];
    const float* WQ_b = (const float*)d_in[5];
    const float* WK_b = (const float*)d_in[7];
    const float* WV_b = (const float*)d_in[9];
    const float* WO_b = (const float*)d_in[11];
    float* out = (float*)d_out;

    cudaFuncSetAttribute(qkv_gemm, cudaFuncAttributeMaxDynamicSharedMemorySize,
                         2 * STAGE_B);
    cudaFuncSetAttribute(out_gemm, cudaFuncAttributeMaxDynamicSharedMemorySize,
                         2 * STAGE_B);
    cudaFuncSetAttribute(attn_mma, cudaFuncAttributeMaxDynamicSharedMemorySize,
                         ASMEM);

    // Mask preprocessing
    pack_mask<<<BB * LL * (LL / 32) / 256, 256>>>(maskp);
    mask_flags<<<dim3(8, 8, 8), 128>>>();

    // Splits
    split_w<<<dim3(DD * DD / 4 / 256, 1, 4), 256>>>(
        (const float*)d_in[4], (const float*)d_in[6],
        (const float*)d_in[8], (const float*)d_in[10]);
    split_x<<<dim3(MM * DD / 4 / 256, 1, 3), 256>>>(Query, Key, Value);

    // Fused Q/K/V projections
    qkv_gemm<<<dim3(DD / 128, MM / 128, 3), 256, 2 * STAGE_B>>>(WQ_b, WK_b, WV_b);

    // Attention
    attn_mma<<<dim3(LL / 128, HH, BB), 256, ASMEM>>>();

    // Output projection
    out_gemm<<<dim3(DD / 128, MM / 128), 256, 2 * STAGE_B>>>(WO_b, out);
}

// round 8
// speedup vs baseline: 2.4661x; 2.4661x over previous
#include <cuda_runtime.h>
#include <cuda_fp16.h>
#include <cstdint>

// Problem constants
#define BB 8
#define LL 1024
#define DD 768
#define HH 12
#define DHH 64
#define MM (BB*LL)   // 8192
#define LOG2E 1.4426950408889634f

// ---------------------------------------------------------------------------
// Scratch (device globals — no allocation allowed)
// ---------------------------------------------------------------------------
__device__ __half g_q16[BB*HH*LL*DHH];     // [B,H,L,Dh], pre-scaled
__device__ __half g_k16[BB*HH*LL*DHH];
__device__ __half g_v16[BB*HH*LL*DHH];
__device__ __half g_c16[MM*DD];            // attention context [M, D]
__device__ __half g_x16[3][MM*DD];         // fp16 inputs
__device__ __half g_w16[4][DD*DD];         // fp16 weights
__device__ uint32_t g_mbits[BB*LL*(LL/32)];
__device__ unsigned char g_mflags[BB*8*8];

// ---------------------------------------------------------------------------
// PTX helpers — baseline (non-'a') features only
// ---------------------------------------------------------------------------
__device__ __forceinline__ uint32_t smem_u32(const void* p) {
    uint32_t a;
    asm("{ .reg .u64 t; cvta.to.shared.u64 t, %1; cvt.u32.u64 %0, t; }"
        : "=r"(a) : "l"(p));
    return a;
}
__device__ __forceinline__ void cp_async16(uint32_t saddr, const void* gptr) {
    asm volatile("cp.async.cg.shared.global [%0], [%1], 16;"
                 :: "r"(saddr), "l"(gptr) : "memory");
}
__device__ __forceinline__ void cp_commit() {
    asm volatile("cp.async.commit_group;" ::: "memory");
}
template<int N>
__device__ __forceinline__ void cp_wait() {
    asm volatile("cp.async.wait_group %0;" :: "n"(N) : "memory");
}
__device__ __forceinline__ void ldmatrix_x4(uint32_t& r0, uint32_t& r1,
                                            uint32_t& r2, uint32_t& r3,
                                            uint32_t addr) {
    asm volatile("ldmatrix.sync.aligned.m8n8.x4.shared.b16 {%0,%1,%2,%3}, [%4];"
                 : "=r"(r0), "=r"(r1), "=r"(r2), "=r"(r3) : "r"(addr));
}
__device__ __forceinline__ void ldmatrix_x4_t(uint32_t& r0, uint32_t& r1,
                                              uint32_t& r2, uint32_t& r3,
                                              uint32_t addr) {
    asm volatile("ldmatrix.sync.aligned.m8n8.x4.trans.shared.b16 {%0,%1,%2,%3}, [%4];"
                 : "=r"(r0), "=r"(r1), "=r"(r2), "=r"(r3) : "r"(addr));
}
__device__ __forceinline__ void mma_f16(float* c, const uint32_t* a,
                                        uint32_t b0, uint32_t b1) {
    asm volatile(
        "mma.sync.aligned.m16n8k16.row.col.f32.f16.f16.f32 "
        "{%0,%1,%2,%3}, {%4,%5,%6,%7}, {%8,%9}, {%0,%1,%2,%3};"
        : "+f"(c[0]), "+f"(c[1]), "+f"(c[2]), "+f"(c[3])
        : "r"(a[0]), "r"(a[1]), "r"(a[2]), "r"(a[3]), "r"(b0), "r"(b1));
}
__device__ __forceinline__ uint32_t pack_h2(float a, float b) {
    __half2 h = __floats2half2_rn(a, b);
    return *reinterpret_cast<uint32_t*>(&h);
}

// ---------------------------------------------------------------------------
// Mask preprocessing
// ---------------------------------------------------------------------------
__global__ __launch_bounds__(256)
void pack_mask(const unsigned char* __restrict__ mask)
{
    int i = blockIdx.x * blockDim.x + threadIdx.x;
    const uint4* p = reinterpret_cast<const uint4*>(mask + (size_t)i * 32);
    uint4 u0 = p[0], u1 = p[1];
    uint32_t ws[8] = {u0.x, u0.y, u0.z, u0.w, u1.x, u1.y, u1.z, u1.w};
    uint32_t r = 0;
    #pragma unroll
    for (int w = 0; w < 8; w++)
        #pragma unroll
        for (int k = 0; k < 4; k++)
            if ((ws[w] >> (8 * k)) & 0xFFu) r |= 1u << (w * 4 + k);
    g_mbits[i] = r;
}

__global__ __launch_bounds__(128)
void mask_flags()
{
    int kt = blockIdx.x, qt = blockIdx.y, b = blockIdx.z;
    int row = qt * 128 + threadIdx.x;
    const uint32_t* p = g_mbits + ((size_t)(b * LL + row)) * (LL / 32) + kt * 4;
    uint32_t v = p[0] | p[1] | p[2] | p[3];
    int any = __syncthreads_or(v != 0);
    if (threadIdx.x == 0) g_mflags[(b * 8 + qt) * 8 + kt] = (unsigned char)any;
}

// ---------------------------------------------------------------------------
// fp32 -> fp16 converts
// ---------------------------------------------------------------------------
__device__ __forceinline__ void cvt16(const float* src, __half* dst, int i)
{
    float4 f = reinterpret_cast<const float4*>(src)[i];
    uint32_t* dp = reinterpret_cast<uint32_t*>(dst);
    dp[2*i]   = pack_h2(f.x, f.y);
    dp[2*i+1] = pack_h2(f.z, f.w);
}

__global__ __launch_bounds__(256)
void split_x(const float* __restrict__ q, const float* __restrict__ k,
             const float* __restrict__ v)
{
    int z = blockIdx.z;
    const float* src = (z == 0) ? q : (z == 1) ? k : v;
    cvt16(src, g_x16[z], blockIdx.x * blockDim.x + threadIdx.x);
}

__global__ __launch_bounds__(256)
void split_w(const float* __restrict__ w0, const float* __restrict__ w1,
             const float* __restrict__ w2, const float* __restrict__ w3)
{
    int z = blockIdx.z;
    const float* src = (z == 0) ? w0 : (z == 1) ? w1 : (z == 2) ? w2 : w3;
    cvt16(src, g_w16[z], blockIdx.x * blockDim.x + threadIdx.x);
}

// ---------------------------------------------------------------------------
// GEMM core: single fp16 term. Block 128x128, BK=32, 8 warps, occ 2.
// ---------------------------------------------------------------------------
#define PH      80                       // smem pitch: 64B data + 16 pad
#define TILE_B  (128 * PH)               // 10240
#define STAGE_B (2 * TILE_B)             // A + B = 20480
#define NCHUNK  (DD / 32)                // 24

__device__ __forceinline__ void gemm_core(
    const __half* __restrict__ A, const __half* __restrict__ B,
    uint32_t sbase, int tid, float acc[2][8][4])
{
    const int wid = tid >> 5, lane = tid & 31;
    const int wm = wid & 3, wn = wid >> 2;

    auto load_chunk = [&](int kc, int st) {
        const int k0 = kc * 32;
        #pragma unroll
        for (int t = 0; t < 4; t++) {
            int id   = tid + t * 256;        // 0..1023
            int tile = id >> 9;              // 0: A, 1: B
            int rem  = id & 511;
            int row  = rem >> 2;
            int seg  = rem & 3;
            const __half* g = (tile ? B : A) + (size_t)row * DD + k0 + seg * 8;
            uint32_t s = sbase + st * STAGE_B + tile * TILE_B + row * PH + seg * 16;
            cp_async16(s, g);
        }
        cp_commit();
    };

    load_chunk(0, 0);

    const int lrow = lane & 15;
    const int lhalf = lane >> 4;

    #pragma unroll 1
    for (int c = 0; c < NCHUNK; c++) {
        const int s = c & 1;
        if (c + 1 < NCHUNK) { load_chunk(c + 1, s ^ 1); cp_wait<1>(); }
        else                { cp_wait<0>(); }
        __syncthreads();

        const uint32_t stg = sbase + s * STAGE_B;

        #pragma unroll
        for (int ks = 0; ks < 2; ks++) {
            const int seg = ks * 2 + lhalf;
            uint32_t ah[2][4];
            #pragma unroll
            for (int mf = 0; mf < 2; mf++) {
                uint32_t off = (uint32_t)((wm * 32 + mf * 16 + lrow) * PH + seg * 16);
                ldmatrix_x4(ah[mf][0], ah[mf][1], ah[mf][2], ah[mf][3], stg + off);
            }
            #pragma unroll
            for (int ng = 0; ng < 4; ng++) {
                uint32_t off = (uint32_t)((wn * 64 + ng * 16 + lrow) * PH + seg * 16);
                uint32_t b0, b1, b2, b3;
                ldmatrix_x4(b0, b1, b2, b3, stg + TILE_B + off);
                #pragma unroll
                for (int mf = 0; mf < 2; mf++) {
                    mma_f16(acc[mf][2*ng  ], ah[mf], b0, b2);
                    mma_f16(acc[mf][2*ng+1], ah[mf], b1, b3);
                }
            }
        }
        __syncthreads();
    }
}

// Fused Q/K/V projection GEMMs -> fp16 scattered [B,H,L,Dh].
__global__ __launch_bounds__(256, 2)
void qkv_gemm(const float* __restrict__ bq, const float* __restrict__ bk,
              const float* __restrict__ bv)
{
    extern __shared__ __align__(128) char smem[];
    const int z = blockIdx.z;
    const int m0 = blockIdx.y * 128, n0 = blockIdx.x * 128;
    const int tid = threadIdx.x;
    const int wid = tid >> 5, lane = tid & 31;
    const int wm = wid & 3, wn = wid >> 2;

    const float* bias = (z == 0) ? bq : (z == 1) ? bk : bv;
    __half* oh = (z == 0) ? g_q16 : (z == 1) ? g_k16 : g_v16;
    const float scale = (z == 0) ? 0.125f * LOG2E : 1.0f;

    float acc[2][8][4];
    #pragma unroll
    for (int i = 0; i < 2; i++)
        #pragma unroll
        for (int j = 0; j < 8; j++)
            #pragma unroll
            for (int k = 0; k < 4; k++) acc[i][j][k] = 0.f;

    gemm_core(g_x16[z] + (size_t)m0 * DD, g_w16[z] + (size_t)n0 * DD,
              smem_u32(smem), tid, acc);

    #pragma unroll
    for (int nf = 0; nf < 8; nf++) {
        const int col = n0 + wn * 64 + nf * 8 + (lane & 3) * 2;
        const float b0 = bias[col], b1 = bias[col + 1];
        #pragma unroll
        for (int mf = 0; mf < 2; mf++) {
            const int r0 = m0 + wm * 32 + mf * 16 + (lane >> 2);
            const float* a = acc[mf][nf];
            #pragma unroll
            for (int half = 0; half < 2; half++) {
                const int m = r0 + half * 8;
                uint32_t hp = pack_h2((a[2*half] + b0) * scale,
                                      (a[2*half+1] + b1) * scale);
                int bb = m >> 10, l = m & 1023;
                int hh = col >> 6, d = col & 63;
                size_t idx = (((size_t)(bb * HH + hh) << 10) + l) * DHH + d;
                *reinterpret_cast<uint32_t*>(oh + idx) = hp;
            }
        }
    }
}

// Output projection GEMM -> fp32 d_out.
__global__ __launch_bounds__(256, 2)
void out_gemm(const float* __restrict__ bias, float* __restrict__ out)
{
    extern __shared__ __align__(128) char smem[];
    const int m0 = blockIdx.y * 128, n0 = blockIdx.x * 128;
    const int tid = threadIdx.x;
    const int wid = tid >> 5, lane = tid & 31;
    const int wm = wid & 3, wn = wid >> 2;

    float acc[2][8][4];
    #pragma unroll
    for (int i = 0; i < 2; i++)
        #pragma unroll
        for (int j = 0; j < 8; j++)
            #pragma unroll
            for (int k = 0; k < 4; k++) acc[i][j][k] = 0.f;

    gemm_core(g_c16 + (size_t)m0 * DD, g_w16[3] + (size_t)n0 * DD,
              smem_u32(smem), tid, acc);

    #pragma unroll
    for (int nf = 0; nf < 8; nf++) {
        const int col = n0 + wn * 64 + nf * 8 + (lane & 3) * 2;
        const float b0 = bias[col], b1 = bias[col + 1];
        #pragma unroll
        for (int mf = 0; mf < 2; mf++) {
            const int r0 = m0 + wm * 32 + mf * 16 + (lane >> 2);
            const float* a = acc[mf][nf];
            #pragma unroll
            for (int half = 0; half < 2; half++) {
                const int m = r0 + half * 8;
                *reinterpret_cast<float2*>(out + (size_t)m * DD + col)
                    = make_float2(a[2*half] + b0, a[2*half+1] + b1);
            }
        }
    }
}

// ---------------------------------------------------------------------------
// fp16 flash attention. Block = 128 Q rows x (h, b); 8 warps.
// Single-term fp16 QK^T and PV; log2-domain online softmax.
// ---------------------------------------------------------------------------
#define AROWB   144                     // 128B data + 16 pad
#define ATILE_B (128 * AROWB)           // 18432
#define ASMEM   (5 * ATILE_B)           // Q + 2 stages x (K, V) = 92160

__global__ __launch_bounds__(256, 1)
void attn_mma()
{
    extern __shared__ __align__(128) char smem[];
    const uint32_t sb = smem_u32(smem);
    const int tid = threadIdx.x, wid = tid >> 5, lane = tid & 31;
    const int qt = blockIdx.x, h = blockIdx.y, b = blockIdx.z;
    const int q0 = qt * 128;
    const size_t hb = ((size_t)(b * HH + h)) << 16;

    const uint32_t SQ = sb;
    auto stage = [&](int s) { return sb + ATILE_B + (uint32_t)s * 2 * ATILE_B; };

    auto load_tile = [&](const __half* g, uint32_t s) {
        #pragma unroll
        for (int it = 0; it < 4; it++) {
            int id = tid + it * 256;
            int row = id >> 3, seg = id & 7;
            cp_async16(s + row * AROWB + seg * 16, g + (size_t)row * 64 + seg * 8);
        }
    };
    auto load_kv = [&](int t, int s) {
        const size_t off = hb + (size_t)t * 128 * 64;
        uint32_t st = stage(s);
        load_tile(g_k16 + off, st);
        load_tile(g_v16 + off, st + ATILE_B);
        cp_commit();
    };

    load_tile(g_q16 + hb + (size_t)q0 * 64, SQ);
    cp_commit();
    load_kv(0, 0);
    cp_wait<1>();
    __syncthreads();

    const int lr = lane & 15, lh = lane >> 4;
    uint32_t qf[4][4];
    #pragma unroll
    for (int ks = 0; ks < 4; ks++) {
        uint32_t off = (uint32_t)((wid * 16 + lr) * AROWB + ks * 32 + lh * 16);
        ldmatrix_x4(qf[ks][0], qf[ks][1], qf[ks][2], qf[ks][3], SQ + off);
    }

    float mA = -INFINITY, mB = -INFINITY, lA = 0.f, lB = 0.f;
    float o[8][4];
    #pragma unroll
    for (int i = 0; i < 8; i++)
        #pragma unroll
        for (int j = 0; j < 4; j++) o[i][j] = 0.f;

    const unsigned char* flagp = g_mflags + (b * 8 + qt) * 8;

    #pragma unroll 1
    for (int t = 0; t < 8; t++) {
        if (t < 7) { load_kv(t + 1, (t + 1) & 1); cp_wait<1>(); }
        else       { cp_wait<0>(); }
        __syncthreads();
        const uint32_t st = stage(t & 1);

        // ---- S = Q @ K^T ----
        float s[16][4];
        #pragma unroll
        for (int j = 0; j < 16; j++)
            #pragma unroll
            for (int k = 0; k < 4; k++) s[j][k] = 0.f;

        #pragma unroll
        for (int ks = 0; ks < 4; ks++) {
            #pragma unroll
            for (int ng = 0; ng < 8; ng++) {
                uint32_t off = (uint32_t)((ng * 16 + lr) * AROWB + ks * 32 + lh * 16);
                uint32_t k0, k1, k2, k3;
                ldmatrix_x4(k0, k1, k2, k3, st + off);
                mma_f16(s[2*ng  ], qf[ks], k0, k2);
                mma_f16(s[2*ng+1], qf[ks], k1, k3);
            }
        }

        // ---- mask (rare path) ----
        if (flagp[t]) {
            const uint32_t* mr = g_mbits
                + ((size_t)(b * LL + q0 + wid * 16 + (lane >> 2))) * (LL / 32) + t * 4;
            uint32_t wA[4], wB[4];
            #pragma unroll
            for (int ww = 0; ww < 4; ww++) { wA[ww] = mr[ww]; wB[ww] = mr[8 * (LL/32) + ww]; }
            #pragma unroll
            for (int j = 0; j < 16; j++) {
                int bp = (j & 3) * 8 + (lane & 3) * 2;
                uint32_t a = wA[j >> 2], bw = wB[j >> 2];
                if ((a  >> bp)      & 1u) s[j][0] = -INFINITY;
                if ((a  >> (bp+1))  & 1u) s[j][1] = -INFINITY;
                if ((bw >> bp)      & 1u) s[j][2] = -INFINITY;
                if ((bw >> (bp+1))  & 1u) s[j][3] = -INFINITY;
            }
        }

        // ---- online softmax (log2 domain) ----
        float mxA = -INFINITY, mxB = -INFINITY;
        #pragma unroll
        for (int j = 0; j < 16; j++) {
            mxA = fmaxf(mxA, fmaxf(s[j][0], s[j][1]));
            mxB = fmaxf(mxB, fmaxf(s[j][2], s[j][3]));
        }
        mxA = fmaxf(mxA, __shfl_xor_sync(0xffffffffu, mxA, 1));
        mxA = fmaxf(mxA, __shfl_xor_sync(0xffffffffu, mxA, 2));
        mxB = fmaxf(mxB, __shfl_xor_sync(0xffffffffu, mxB, 1));
        mxB = fmaxf(mxB, __shfl_xor_sync(0xffffffffu, mxB, 2));
        float mnA = fmaxf(mA, mxA), mnB = fmaxf(mB, mxB);
        float aA = (mA == -INFINITY) ? 0.f : exp2f(mA - mnA);
        float aB = (mB == -INFINITY) ? 0.f : exp2f(mB - mnB);
        float subA = (mnA == -INFINITY) ? 0.f : mnA;
        float subB = (mnB == -INFINITY) ? 0.f : mnB;
        float sA = 0.f, sB = 0.f;
        #pragma unroll
        for (int j = 0; j < 16; j++) {
            s[j][0] = exp2f(s[j][0] - subA);
            s[j][1] = exp2f(s[j][1] - subA);
            s[j][2] = exp2f(s[j][2] - subB);
            s[j][3] = exp2f(s[j][3] - subB);
            sA += s[j][0] + s[j][1];
            sB += s[j][2] + s[j][3];
        }
        sA += __shfl_xor_sync(0xffffffffu, sA, 1);
        sA += __shfl_xor_sync(0xffffffffu, sA, 2);
        sB += __shfl_xor_sync(0xffffffffu, sB, 1);
        sB += __shfl_xor_sync(0xffffffffu, sB, 2);
        lA = lA * aA + sA; lB = lB * aB + sB;
        mA = mnA; mB = mnB;
        #pragma unroll
        for (int nf = 0; nf < 8; nf++) {
            o[nf][0] *= aA; o[nf][1] *= aA;
            o[nf][2] *= aB; o[nf][3] *= aB;
        }

        // ---- O += P @ V ----
        #pragma unroll
        for (int ks = 0; ks < 8; ks++) {
            uint32_t ap[4];
            ap[0] = pack_h2(s[2*ks  ][0], s[2*ks  ][1]);
            ap[1] = pack_h2(s[2*ks  ][2], s[2*ks  ][3]);
            ap[2] = pack_h2(s[2*ks+1][0], s[2*ks+1][1]);
            ap[3] = pack_h2(s[2*ks+1][2], s[2*ks+1][3]);
            #pragma unroll
            for (int ng = 0; ng < 4; ng++) {
                uint32_t voff = (uint32_t)((ks * 16 + lr) * AROWB + ng * 32 + lh * 16);
                uint32_t v0, v1, v2, v3;
                ldmatrix_x4_t(v0, v1, v2, v3, st + ATILE_B + voff);
                mma_f16(o[2*ng  ], ap, v0, v1);
                mma_f16(o[2*ng+1], ap, v2, v3);
            }
        }
        __syncthreads();
    }

    // ---- epilogue: normalize, write ctx fp16 [M, D] ----
    float iA = (lA > 0.f) ? (1.f / lA) : 0.f;
    float iB = (lB > 0.f) ? (1.f / lB) : 0.f;
    size_t rowA = (size_t)b * LL + q0 + wid * 16 + (lane >> 2);
    size_t rowB = rowA + 8;
    #pragma unroll
    for (int nf = 0; nf < 8; nf++) {
        int col = h * 64 + nf * 8 + (lane & 3) * 2;
        *reinterpret_cast<uint32_t*>(g_c16 + rowA * DD + col)
            = pack_h2(o[nf][0] * iA, o[nf][1] * iA);
        *reinterpret_cast<uint32_t*>(g_c16 + rowB * DD + col)
            = pack_h2(o[nf][2] * iB, o[nf][3] * iB);
    }
}

// ---------------------------------------------------------------------------
extern "C" void kernel_launch(void* const* d_in, const int* in_sizes, int n_in,
                              void* d_out, int out_size)
{
    const float* Query = (const float*)d_in[0];
    const float* Key   = (const float*)d_in[1];
    const float* Value = (const float*)d_in[2];
    const unsigned char* maskp = (const unsigned char*)d_in[3];
    const float* WQ_b = (const float*)d_in[5];
    const float* WK_b = (const float*)d_in[7];
    const float* WV_b = (const float*)d_in[9];
    const float* WO_b = (const float*)d_in[11];
    float* out = (float*)d_out;

    cudaFuncSetAttribute(qkv_gemm, cudaFuncAttributeMaxDynamicSharedMemorySize,
                         2 * STAGE_B);
    cudaFuncSetAttribute(out_gemm, cudaFuncAttributeMaxDynamicSharedMemorySize,
                         2 * STAGE_B);
    cudaFuncSetAttribute(attn_mma, cudaFuncAttributeMaxDynamicSharedMemorySize,
                         ASMEM);

    // Mask preprocessing
    pack_mask<<<BB * LL * (LL / 32) / 256, 256>>>(maskp);
    mask_flags<<<dim3(8, 8, 8), 128>>>();

    // fp16 converts
    split_w<<<dim3(DD * DD / 4 / 256, 1, 4), 256>>>(
        (const float*)d_in[4], (const float*)d_in[6],
        (const float*)d_in[8], (const float*)d_in[10]);
    split_x<<<dim3(MM * DD / 4 / 256, 1, 3), 256>>>(Query, Key, Value);

    // Fused Q/K/V projections
    qkv_gemm<<<dim3(DD / 128, MM / 128, 3), 256, 2 * STAGE_B>>>(WQ_b, WK_b, WV_b);

    // Attention
    attn_mma<<<dim3(LL / 128, HH, BB), 256, ASMEM>>>();

    // Output projection
    out_gemm<<<dim3(DD / 128, MM / 128), 256, 2 * STAGE_B>>>(WO_b, out);
}

// round 9
// speedup vs baseline: 2.7143x; 1.1007x over previous
#include <cuda_runtime.h>
#include <cuda_fp16.h>
#include <cstdint>

// Problem constants
#define BB 8
#define LL 1024
#define DD 768
#define HH 12
#define DHH 64
#define MM (BB*LL)   // 8192
#define LOG2E 1.4426950408889634f

// ---------------------------------------------------------------------------
// Scratch (device globals — no allocation allowed)
// ---------------------------------------------------------------------------
__device__ __half g_q16[BB*HH*LL*DHH];     // [B,H,L,Dh], pre-scaled by log2e/8
__device__ __half g_k16[BB*HH*LL*DHH];
__device__ __half g_v16[BB*HH*LL*DHH];
__device__ __half g_c16[MM*DD];            // attention context [M, D]
__device__ __half g_w16[4][DD*DD];         // fp16 weights
__device__ uint32_t g_mbits[BB*LL*(LL/32)];
__device__ unsigned char g_mflags[BB*8*8];

// ---------------------------------------------------------------------------
// PTX helpers — baseline (non-'a') features only
// ---------------------------------------------------------------------------
__device__ __forceinline__ uint32_t smem_u32(const void* p) {
    uint32_t a;
    asm("{ .reg .u64 t; cvta.to.shared.u64 t, %1; cvt.u32.u64 %0, t; }"
        : "=r"(a) : "l"(p));
    return a;
}
__device__ __forceinline__ void cp_async16(uint32_t saddr, const void* gptr) {
    asm volatile("cp.async.cg.shared.global [%0], [%1], 16;"
                 :: "r"(saddr), "l"(gptr) : "memory");
}
__device__ __forceinline__ void cp_commit() {
    asm volatile("cp.async.commit_group;" ::: "memory");
}
template<int N>
__device__ __forceinline__ void cp_wait() {
    asm volatile("cp.async.wait_group %0;" :: "n"(N) : "memory");
}
__device__ __forceinline__ void ldmatrix_x4(uint32_t& r0, uint32_t& r1,
                                            uint32_t& r2, uint32_t& r3,
                                            uint32_t addr) {
    asm volatile("ldmatrix.sync.aligned.m8n8.x4.shared.b16 {%0,%1,%2,%3}, [%4];"
                 : "=r"(r0), "=r"(r1), "=r"(r2), "=r"(r3) : "r"(addr));
}
__device__ __forceinline__ void ldmatrix_x4_t(uint32_t& r0, uint32_t& r1,
                                              uint32_t& r2, uint32_t& r3,
                                              uint32_t addr) {
    asm volatile("ldmatrix.sync.aligned.m8n8.x4.trans.shared.b16 {%0,%1,%2,%3}, [%4];"
                 : "=r"(r0), "=r"(r1), "=r"(r2), "=r"(r3) : "r"(addr));
}
__device__ __forceinline__ void mma_f16(float* c, const uint32_t* a,
                                        uint32_t b0, uint32_t b1) {
    asm volatile(
        "mma.sync.aligned.m16n8k16.row.col.f32.f16.f16.f32 "
        "{%0,%1,%2,%3}, {%4,%5,%6,%7}, {%8,%9}, {%0,%1,%2,%3};"
        : "+f"(c[0]), "+f"(c[1]), "+f"(c[2]), "+f"(c[3])
        : "r"(a[0]), "r"(a[1]), "r"(a[2]), "r"(a[3]), "r"(b0), "r"(b1));
}
__device__ __forceinline__ uint32_t pack_h2(float a, float b) {
    __half2 h = __floats2half2_rn(a, b);
    return *reinterpret_cast<uint32_t*>(&h);
}

// ---------------------------------------------------------------------------
// Mask preprocessing — single pass: pack bits + per-tile flag.
// One block per (kt, qt, b) 128x128 tile.
// ---------------------------------------------------------------------------
__global__ __launch_bounds__(256)
void prep_mask(const unsigned char* __restrict__ mask)
{
    const int kt = blockIdx.x, qt = blockIdx.y, b = blockIdx.z;
    uint32_t any = 0;
    #pragma unroll
    for (int k = 0; k < 2; k++) {
        int widx = threadIdx.x * 2 + k;      // 0..511
        int row  = widx >> 2;                // 0..127
        int wc   = widx & 3;                 // word-in-tile-row
        const uint4* p = reinterpret_cast<const uint4*>(
            mask + ((size_t)(b * LL + qt * 128 + row)) * LL + kt * 128 + wc * 32);
        uint4 u0 = p[0], u1 = p[1];
        uint32_t ws[8] = {u0.x, u0.y, u0.z, u0.w, u1.x, u1.y, u1.z, u1.w};
        uint32_t r = 0;
        #pragma unroll
        for (int w = 0; w < 8; w++)
            #pragma unroll
            for (int kk = 0; kk < 4; kk++)
                if ((ws[w] >> (8 * kk)) & 0xFFu) r |= 1u << (w * 4 + kk);
        g_mbits[((size_t)(b * LL + qt * 128 + row)) * (LL / 32) + kt * 4 + wc] = r;
        any |= r;
    }
    int f = __syncthreads_or(any != 0);
    if (threadIdx.x == 0) g_mflags[(b * 8 + qt) * 8 + kt] = (unsigned char)f;
}

// ---------------------------------------------------------------------------
// Weight fp32 -> fp16 convert (small: 4 x 2.25 MB)
// ---------------------------------------------------------------------------
__global__ __launch_bounds__(256)
void split_w(const float* __restrict__ w0, const float* __restrict__ w1,
             const float* __restrict__ w2, const float* __restrict__ w3)
{
    int z = blockIdx.z;
    const float* src = (z == 0) ? w0 : (z == 1) ? w1 : (z == 2) ? w2 : w3;
    int i = blockIdx.x * blockDim.x + threadIdx.x;
    float4 f = reinterpret_cast<const float4*>(src)[i];
    uint32_t* dp = reinterpret_cast<uint32_t*>(g_w16[z]);
    dp[2*i]   = pack_h2(f.x, f.y);
    dp[2*i+1] = pack_h2(f.z, f.w);
}

// ---------------------------------------------------------------------------
// Fused Q/K/V projection GEMMs. A = fp32 input (converted in-kernel),
// B = fp16 weights. Block 128x128, BK=32, 8 warps, occ 2.
// Epilogue: +bias, *scale, fp16 scatter to [B,H,L,Dh].
// ---------------------------------------------------------------------------
#define PH      80                       // smem pitch: 64B data + 16 pad
#define TILE_B  (128 * PH)               // 10240
#define STAGE_B (2 * TILE_B)             // A + B = 20480
#define NCHUNK  (DD / 32)                // 24

__global__ __launch_bounds__(256, 2)
void qkv_gemm(const float* __restrict__ Q, const float* __restrict__ K,
              const float* __restrict__ V,
              const float* __restrict__ bq, const float* __restrict__ bk,
              const float* __restrict__ bv)
{
    extern __shared__ __align__(128) char smem[];
    const uint32_t sbase = smem_u32(smem);
    const int z = blockIdx.z;
    const int m0 = blockIdx.y * 128, n0 = blockIdx.x * 128;
    const int tid = threadIdx.x;
    const int wid = tid >> 5, lane = tid & 31;
    const int wm = wid & 3, wn = wid >> 2;

    const float* A = ((z == 0) ? Q : (z == 1) ? K : V) + (size_t)m0 * DD;
    const __half* B = g_w16[z] + (size_t)n0 * DD;
    const float* bias = (z == 0) ? bq : (z == 1) ? bk : bv;
    __half* oh = (z == 0) ? g_q16 : (z == 1) ? g_k16 : g_v16;
    const float scale = (z == 0) ? 0.125f * LOG2E : 1.0f;

    // A register prefetch: thread covers 4 float4 (row = id>>3, fseg = id&7)
    const int arow[4] = { tid >> 3, (tid + 256) >> 3, (tid + 512) >> 3, (tid + 768) >> 3 };
    const int afsg = tid & 7;

    float4 abuf[4];
    auto ldg_A = [&](int kc) {
        const float* g = A + kc * 32 + afsg * 4;
        #pragma unroll
        for (int t = 0; t < 4; t++)
            abuf[t] = *reinterpret_cast<const float4*>(g + (size_t)arow[t] * DD);
    };
    auto sts_A = [&](int st) {
        char* base = smem + st * STAGE_B;
        #pragma unroll
        for (int t = 0; t < 4; t++) {
            uint2 h;
            h.x = pack_h2(abuf[t].x, abuf[t].y);
            h.y = pack_h2(abuf[t].z, abuf[t].w);
            *reinterpret_cast<uint2*>(base + arow[t] * PH + afsg * 8) = h;
        }
    };
    auto cp_B = [&](int kc, int st) {
        #pragma unroll
        for (int t = 0; t < 2; t++) {
            int id = tid + t * 256;          // 0..511
            int row = id >> 2, seg = id & 3;
            cp_async16(sbase + st * STAGE_B + TILE_B + row * PH + seg * 16,
                       B + (size_t)row * DD + kc * 32 + seg * 8);
        }
        cp_commit();
    };

    float acc[2][8][4];
    #pragma unroll
    for (int i = 0; i < 2; i++)
        #pragma unroll
        for (int j = 0; j < 8; j++)
            #pragma unroll
            for (int k = 0; k < 4; k++) acc[i][j][k] = 0.f;

    ldg_A(0);
    cp_B(0, 0);

    const int lrow = lane & 15;
    const int lhalf = lane >> 4;

    #pragma unroll 1
    for (int c = 0; c < NCHUNK; c++) {
        const int s = c & 1;
        sts_A(s);                            // abuf holds chunk c
        if (c + 1 < NCHUNK) {
            ldg_A(c + 1);                    // prefetch next chunk (hidden under MMAs)
            cp_B(c + 1, s ^ 1);
            cp_wait<1>();
        } else {
            cp_wait<0>();
        }
        __syncthreads();

        const uint32_t stg = sbase + s * STAGE_B;
        #pragma unroll
        for (int ks = 0; ks < 2; ks++) {
            const int seg = ks * 2 + lhalf;
            uint32_t ah[2][4];
            #pragma unroll
            for (int mf = 0; mf < 2; mf++) {
                uint32_t off = (uint32_t)((wm * 32 + mf * 16 + lrow) * PH + seg * 16);
                ldmatrix_x4(ah[mf][0], ah[mf][1], ah[mf][2], ah[mf][3], stg + off);
            }
            #pragma unroll
            for (int ng = 0; ng < 4; ng++) {
                uint32_t off = (uint32_t)((wn * 64 + ng * 16 + lrow) * PH + seg * 16);
                uint32_t b0, b1, b2, b3;
                ldmatrix_x4(b0, b1, b2, b3, stg + TILE_B + off);
                #pragma unroll
                for (int mf = 0; mf < 2; mf++) {
                    mma_f16(acc[mf][2*ng  ], ah[mf], b0, b2);
                    mma_f16(acc[mf][2*ng+1], ah[mf], b1, b3);
                }
            }
        }
        __syncthreads();
    }

    #pragma unroll
    for (int nf = 0; nf < 8; nf++) {
        const int col = n0 + wn * 64 + nf * 8 + (lane & 3) * 2;
        const float b0 = bias[col], b1 = bias[col + 1];
        #pragma unroll
        for (int mf = 0; mf < 2; mf++) {
            const int r0 = m0 + wm * 32 + mf * 16 + (lane >> 2);
            const float* a = acc[mf][nf];
            #pragma unroll
            for (int half = 0; half < 2; half++) {
                const int m = r0 + half * 8;
                uint32_t hp = pack_h2((a[2*half] + b0) * scale,
                                      (a[2*half+1] + b1) * scale);
                int bb = m >> 10, l = m & 1023;
                int hh = col >> 6, d = col & 63;
                size_t idx = (((size_t)(bb * HH + hh) << 10) + l) * DHH + d;
                *reinterpret_cast<uint32_t*>(oh + idx) = hp;
            }
        }
    }
}

// ---------------------------------------------------------------------------
// Output projection GEMM: A = ctx fp16, B = fp16 weights -> fp32 d_out.
// ---------------------------------------------------------------------------
__global__ __launch_bounds__(256, 2)
void out_gemm(const float* __restrict__ bias, float* __restrict__ out)
{
    extern __shared__ __align__(128) char smem[];
    const uint32_t sbase = smem_u32(smem);
    const int m0 = blockIdx.y * 128, n0 = blockIdx.x * 128;
    const int tid = threadIdx.x;
    const int wid = tid >> 5, lane = tid & 31;
    const int wm = wid & 3, wn = wid >> 2;

    const __half* A = g_c16 + (size_t)m0 * DD;
    const __half* B = g_w16[3] + (size_t)n0 * DD;

    auto load_chunk = [&](int kc, int st) {
        const int k0 = kc * 32;
        #pragma unroll
        for (int t = 0; t < 4; t++) {
            int id   = tid + t * 256;
            int tile = id >> 9;
            int rem  = id & 511;
            int row  = rem >> 2;
            int seg  = rem & 3;
            const __half* g = (tile ? B : A) + (size_t)row * DD + k0 + seg * 8;
            cp_async16(sbase + st * STAGE_B + tile * TILE_B + row * PH + seg * 16, g);
        }
        cp_commit();
    };

    float acc[2][8][4];
    #pragma unroll
    for (int i = 0; i < 2; i++)
        #pragma unroll
        for (int j = 0; j < 8; j++)
            #pragma unroll
            for (int k = 0; k < 4; k++) acc[i][j][k] = 0.f;

    load_chunk(0, 0);

    const int lrow = lane & 15;
    const int lhalf = lane >> 4;

    #pragma unroll 1
    for (int c = 0; c < NCHUNK; c++) {
        const int s = c & 1;
        if (c + 1 < NCHUNK) { load_chunk(c + 1, s ^ 1); cp_wait<1>(); }
        else                { cp_wait<0>(); }
        __syncthreads();

        const uint32_t stg = sbase + s * STAGE_B;
        #pragma unroll
        for (int ks = 0; ks < 2; ks++) {
            const int seg = ks * 2 + lhalf;
            uint32_t ah[2][4];
            #pragma unroll
            for (int mf = 0; mf < 2; mf++) {
                uint32_t off = (uint32_t)((wm * 32 + mf * 16 + lrow) * PH + seg * 16);
                ldmatrix_x4(ah[mf][0], ah[mf][1], ah[mf][2], ah[mf][3], stg + off);
            }
            #pragma unroll
            for (int ng = 0; ng < 4; ng++) {
                uint32_t off = (uint32_t)((wn * 64 + ng * 16 + lrow) * PH + seg * 16);
                uint32_t b0, b1, b2, b3;
                ldmatrix_x4(b0, b1, b2, b3, stg + TILE_B + off);
                #pragma unroll
                for (int mf = 0; mf < 2; mf++) {
                    mma_f16(acc[mf][2*ng  ], ah[mf], b0, b2);
                    mma_f16(acc[mf][2*ng+1], ah[mf], b1, b3);
                }
            }
        }
        __syncthreads();
    }

    #pragma unroll
    for (int nf = 0; nf < 8; nf++) {
        const int col = n0 + wn * 64 + nf * 8 + (lane & 3) * 2;
        const float b0 = bias[col], b1 = bias[col + 1];
        #pragma unroll
        for (int mf = 0; mf < 2; mf++) {
            const int r0 = m0 + wm * 32 + mf * 16 + (lane >> 2);
            const float* a = acc[mf][nf];
            #pragma unroll
            for (int half = 0; half < 2; half++) {
                const int m = r0 + half * 8;
                *reinterpret_cast<float2*>(out + (size_t)m * DD + col)
                    = make_float2(a[2*half] + b0, a[2*half+1] + b1);
            }
        }
    }
}

// ---------------------------------------------------------------------------
// fp16 flash attention. Block = 128 Q rows x (h, b); 8 warps; KV tile 64.
// Occ 2 (smem 54 KB, launch_bounds cap 128 regs).
// ---------------------------------------------------------------------------
#define AROWB   144                     // 128B data + 16 pad
#define QTILE_B (128 * AROWB)           // 18432
#define KTILE_B (64 * AROWB)            // 9216
#define ASMEM   (QTILE_B + 4 * KTILE_B) // 55296

__global__ __launch_bounds__(256, 2)
void attn_mma()
{
    extern __shared__ __align__(128) char smem[];
    const uint32_t sb = smem_u32(smem);
    const int tid = threadIdx.x, wid = tid >> 5, lane = tid & 31;
    const int qt = blockIdx.x, h = blockIdx.y, b = blockIdx.z;
    const int q0 = qt * 128;
    const size_t hb = ((size_t)(b * HH + h)) << 16;

    const uint32_t SQ = sb;
    auto stage = [&](int s) { return sb + QTILE_B + (uint32_t)s * 2 * KTILE_B; };

    auto load_q = [&]() {
        const __half* g = g_q16 + hb + (size_t)q0 * 64;
        #pragma unroll
        for (int it = 0; it < 4; it++) {
            int id = tid + it * 256;
            int row = id >> 3, seg = id & 7;
            cp_async16(SQ + row * AROWB + seg * 16, g + (size_t)row * 64 + seg * 8);
        }
        cp_commit();
    };
    auto load_kv = [&](int t, int s) {
        const size_t off = hb + (size_t)t * 64 * 64;
        uint32_t st = stage(s);
        #pragma unroll
        for (int it = 0; it < 2; it++) {
            int id = tid + it * 256;         // 0..511
            int row = id >> 3, seg = id & 7;
            cp_async16(st + row * AROWB + seg * 16,
                       g_k16 + off + (size_t)row * 64 + seg * 8);
            cp_async16(st + KTILE_B + row * AROWB + seg * 16,
                       g_v16 + off + (size_t)row * 64 + seg * 8);
        }
        cp_commit();
    };

    load_q();
    load_kv(0, 0);
    cp_wait<1>();
    __syncthreads();

    const int lr = lane & 15, lh = lane >> 4;
    uint32_t qf[4][4];
    #pragma unroll
    for (int ks = 0; ks < 4; ks++) {
        uint32_t off = (uint32_t)((wid * 16 + lr) * AROWB + ks * 32 + lh * 16);
        ldmatrix_x4(qf[ks][0], qf[ks][1], qf[ks][2], qf[ks][3], SQ + off);
    }

    float mA = -INFINITY, mB = -INFINITY, lA = 0.f, lB = 0.f;
    float o[8][4];
    #pragma unroll
    for (int i = 0; i < 8; i++)
        #pragma unroll
        for (int j = 0; j < 4; j++) o[i][j] = 0.f;

    const unsigned char* flagp = g_mflags + (b * 8 + qt) * 8;

    #pragma unroll 1
    for (int t = 0; t < 16; t++) {
        if (t < 15) { load_kv(t + 1, (t + 1) & 1); cp_wait<1>(); }
        else        { cp_wait<0>(); }
        __syncthreads();
        const uint32_t st = stage(t & 1);

        // ---- S = Q @ K^T  (64 KV rows) ----
        float s[8][4];
        #pragma unroll
        for (int j = 0; j < 8; j++)
            #pragma unroll
            for (int k = 0; k < 4; k++) s[j][k] = 0.f;

        #pragma unroll
        for (int ks = 0; ks < 4; ks++) {
            #pragma unroll
            for (int ng = 0; ng < 4; ng++) {
                uint32_t off = (uint32_t)((ng * 16 + lr) * AROWB + ks * 32 + lh * 16);
                uint32_t k0, k1, k2, k3;
                ldmatrix_x4(k0, k1, k2, k3, st + off);
                mma_f16(s[2*ng  ], qf[ks], k0, k2);
                mma_f16(s[2*ng+1], qf[ks], k1, k3);
            }
        }

        // ---- mask (rare path; flag at 128-col granularity) ----
        if (flagp[t >> 1]) {
            const uint32_t* mr = g_mbits
                + ((size_t)(b * LL + q0 + wid * 16 + (lane >> 2))) * (LL / 32) + t * 2;
            uint32_t wA[2], wB[2];
            #pragma unroll
            for (int ww = 0; ww < 2; ww++) { wA[ww] = mr[ww]; wB[ww] = mr[8 * (LL/32) + ww]; }
            #pragma unroll
            for (int j = 0; j < 8; j++) {
                int bp = (j & 3) * 8 + (lane & 3) * 2;
                uint32_t a = wA[j >> 2], bw = wB[j >> 2];
                if ((a  >> bp)      & 1u) s[j][0] = -INFINITY;
                if ((a  >> (bp+1))  & 1u) s[j][1] = -INFINITY;
                if ((bw >> bp)      & 1u) s[j][2] = -INFINITY;
                if ((bw >> (bp+1))  & 1u) s[j][3] = -INFINITY;
            }
        }

        // ---- online softmax (log2 domain) ----
        float mxA = -INFINITY, mxB = -INFINITY;
        #pragma unroll
        for (int j = 0; j < 8; j++) {
            mxA = fmaxf(mxA, fmaxf(s[j][0], s[j][1]));
            mxB = fmaxf(mxB, fmaxf(s[j][2], s[j][3]));
        }
        mxA = fmaxf(mxA, __shfl_xor_sync(0xffffffffu, mxA, 1));
        mxA = fmaxf(mxA, __shfl_xor_sync(0xffffffffu, mxA, 2));
        mxB = fmaxf(mxB, __shfl_xor_sync(0xffffffffu, mxB, 1));
        mxB = fmaxf(mxB, __shfl_xor_sync(0xffffffffu, mxB, 2));
        float mnA = fmaxf(mA, mxA), mnB = fmaxf(mB, mxB);
        float aA = (mA == -INFINITY) ? 0.f : exp2f(mA - mnA);
        float aB = (mB == -INFINITY) ? 0.f : exp2f(mB - mnB);
        float subA = (mnA == -INFINITY) ? 0.f : mnA;
        float subB = (mnB == -INFINITY) ? 0.f : mnB;
        float sA = 0.f, sB = 0.f;
        #pragma unroll
        for (int j = 0; j < 8; j++) {
            s[j][0] = exp2f(s[j][0] - subA);
            s[j][1] = exp2f(s[j][1] - subA);
            s[j][2] = exp2f(s[j][2] - subB);
            s[j][3] = exp2f(s[j][3] - subB);
            sA += s[j][0] + s[j][1];
            sB += s[j][2] + s[j][3];
        }
        sA += __shfl_xor_sync(0xffffffffu, sA, 1);
        sA += __shfl_xor_sync(0xffffffffu, sA, 2);
        sB += __shfl_xor_sync(0xffffffffu, sB, 1);
        sB += __shfl_xor_sync(0xffffffffu, sB, 2);
        lA = lA * aA + sA; lB = lB * aB + sB;
        mA = mnA; mB = mnB;
        #pragma unroll
        for (int nf = 0; nf < 8; nf++) {
            o[nf][0] *= aA; o[nf][1] *= aA;
            o[nf][2] *= aB; o[nf][3] *= aB;
        }

        // ---- O += P @ V  (64 KV rows = 4 k-steps) ----
        #pragma unroll
        for (int ks = 0; ks < 4; ks++) {
            uint32_t ap[4];
            ap[0] = pack_h2(s[2*ks  ][0], s[2*ks  ][1]);
            ap[1] = pack_h2(s[2*ks  ][2], s[2*ks  ][3]);
            ap[2] = pack_h2(s[2*ks+1][0], s[2*ks+1][1]);
            ap[3] = pack_h2(s[2*ks+1][2], s[2*ks+1][3]);
            #pragma unroll
            for (int ng = 0; ng < 4; ng++) {
                uint32_t voff = (uint32_t)((ks * 16 + lr) * AROWB + ng * 32 + lh * 16);
                uint32_t v0, v1, v2, v3;
                ldmatrix_x4_t(v0, v1, v2, v3, st + KTILE_B + voff);
                mma_f16(o[2*ng  ], ap, v0, v1);
                mma_f16(o[2*ng+1], ap, v2, v3);
            }
        }
        __syncthreads();
    }

    // ---- epilogue: normalize, write ctx fp16 [M, D] ----
    float iA = (lA > 0.f) ? (1.f / lA) : 0.f;
    float iB = (lB > 0.f) ? (1.f / lB) : 0.f;
    size_t rowA = (size_t)b * LL + q0 + wid * 16 + (lane >> 2);
    size_t rowB = rowA + 8;
    #pragma unroll
    for (int nf = 0; nf < 8; nf++) {
        int col = h * 64 + nf * 8 + (lane & 3) * 2;
        *reinterpret_cast<uint32_t*>(g_c16 + rowA * DD + col)
            = pack_h2(o[nf][0] * iA, o[nf][1] * iA);
        *reinterpret_cast<uint32_t*>(g_c16 + rowB * DD + col)
            = pack_h2(o[nf][2] * iB, o[nf][3] * iB);
    }
}

// ---------------------------------------------------------------------------
extern "C" void kernel_launch(void* const* d_in, const int* in_sizes, int n_in,
                              void* d_out, int out_size)
{
    const float* Query = (const float*)d_in[0];
    const float* Key   = (const float*)d_in[1];
    const float* Value = (const float*)d_in[2];
    const unsigned char* maskp = (const unsigned char*)d_in[3];
    const float* WQ_b = (const float*)d_in[5];
    const float* WK_b = (const float*)d_in[7];
    const float* WV_b = (const float*)d_in[9];
    const float* WO_b = (const float*)d_in[11];
    float* out = (float*)d_out;

    cudaFuncSetAttribute(qkv_gemm, cudaFuncAttributeMaxDynamicSharedMemorySize,
                         2 * STAGE_B);
    cudaFuncSetAttribute(out_gemm, cudaFuncAttributeMaxDynamicSharedMemorySize,
                         2 * STAGE_B);
    cudaFuncSetAttribute(attn_mma, cudaFuncAttributeMaxDynamicSharedMemorySize,
                         ASMEM);

    // Mask: single-pass pack + flags
    prep_mask<<<dim3(8, 8, 8), 256>>>(maskp);

    // Weight converts
    split_w<<<dim3(DD * DD / 4 / 256, 1, 4), 256>>>(
        (const float*)d_in[4], (const float*)d_in[6],
        (const float*)d_in[8], (const float*)d_in[10]);

    // Fused Q/K/V projections (fp32 A converted in-kernel)
    qkv_gemm<<<dim3(DD / 128, MM / 128, 3), 256, 2 * STAGE_B>>>(
        Query, Key, Value, WQ_b, WK_b, WV_b);

    // Attention
    attn_mma<<<dim3(LL / 128, HH, BB), 256, ASMEM>>>();

    // Output projection
    out_gemm<<<dim3(DD / 128, MM / 128), 256, 2 * STAGE_B>>>(WO_b, out);
}

// round 10
// speedup vs baseline: 2.8169x; 1.0378x over previous
#include <cuda_runtime.h>
#include <cuda_fp16.h>
#include <cstdint>

// Problem constants
#define BB 8
#define LL 1024
#define DD 768
#define HH 12
#define DHH 64
#define MM (BB*LL)   // 8192
#define LOG2E 1.4426950408889634f

// ---------------------------------------------------------------------------
// Scratch (device globals — no allocation allowed)
// ---------------------------------------------------------------------------
__device__ __half g_q16[BB*HH*LL*DHH];     // [B,H,L,Dh], pre-scaled by log2e/8
__device__ __half g_k16[BB*HH*LL*DHH];
__device__ __half g_v16[BB*HH*LL*DHH];
__device__ __half g_c16[MM*DD];            // attention context [M, D]
__device__ __half g_w16[4][DD*DD];         // fp16 weights
__device__ uint32_t g_mbits[BB*LL*(LL/32)];
__device__ unsigned char g_mflags[BB*8*8];
__device__ int g_sync[BB*8];               // per-(b, qtile128) completion counters

// ---------------------------------------------------------------------------
// PTX helpers — baseline (non-'a') features only
// ---------------------------------------------------------------------------
__device__ __forceinline__ uint32_t smem_u32(const void* p) {
    uint32_t a;
    asm("{ .reg .u64 t; cvta.to.shared.u64 t, %1; cvt.u32.u64 %0, t; }"
        : "=r"(a) : "l"(p));
    return a;
}
__device__ __forceinline__ void cp_async16(uint32_t saddr, const void* gptr) {
    asm volatile("cp.async.cg.shared.global [%0], [%1], 16;"
                 :: "r"(saddr), "l"(gptr) : "memory");
}
__device__ __forceinline__ void cp_commit() {
    asm volatile("cp.async.commit_group;" ::: "memory");
}
template<int N>
__device__ __forceinline__ void cp_wait() {
    asm volatile("cp.async.wait_group %0;" :: "n"(N) : "memory");
}
__device__ __forceinline__ void ldmatrix_x4(uint32_t& r0, uint32_t& r1,
                                            uint32_t& r2, uint32_t& r3,
                                            uint32_t addr) {
    asm volatile("ldmatrix.sync.aligned.m8n8.x4.shared.b16 {%0,%1,%2,%3}, [%4];"
                 : "=r"(r0), "=r"(r1), "=r"(r2), "=r"(r3) : "r"(addr));
}
__device__ __forceinline__ void ldmatrix_x4_t(uint32_t& r0, uint32_t& r1,
                                              uint32_t& r2, uint32_t& r3,
                                              uint32_t addr) {
    asm volatile("ldmatrix.sync.aligned.m8n8.x4.trans.shared.b16 {%0,%1,%2,%3}, [%4];"
                 : "=r"(r0), "=r"(r1), "=r"(r2), "=r"(r3) : "r"(addr));
}
__device__ __forceinline__ void mma_f16(float* c, const uint32_t* a,
                                        uint32_t b0, uint32_t b1) {
    asm volatile(
        "mma.sync.aligned.m16n8k16.row.col.f32.f16.f16.f32 "
        "{%0,%1,%2,%3}, {%4,%5,%6,%7}, {%8,%9}, {%0,%1,%2,%3};"
        : "+f"(c[0]), "+f"(c[1]), "+f"(c[2]), "+f"(c[3])
        : "r"(a[0]), "r"(a[1]), "r"(a[2]), "r"(a[3]), "r"(b0), "r"(b1));
}
__device__ __forceinline__ uint32_t pack_h2(float a, float b) {
    __half2 h = __floats2half2_rn(a, b);
    return *reinterpret_cast<uint32_t*>(&h);
}

// ---------------------------------------------------------------------------
// Mask preprocessing — single pass: pack bits + per-tile flag; resets g_sync.
// ---------------------------------------------------------------------------
__global__ __launch_bounds__(256)
void prep_mask(const unsigned char* __restrict__ mask)
{
    const int kt = blockIdx.x, qt = blockIdx.y, b = blockIdx.z;
    if (kt == 0 && threadIdx.x == 0) g_sync[b * 8 + qt] = 0;
    uint32_t any = 0;
    #pragma unroll
    for (int k = 0; k < 2; k++) {
        int widx = threadIdx.x * 2 + k;      // 0..511
        int row  = widx >> 2;                // 0..127
        int wc   = widx & 3;
        const uint4* p = reinterpret_cast<const uint4*>(
            mask + ((size_t)(b * LL + qt * 128 + row)) * LL + kt * 128 + wc * 32);
        uint4 u0 = p[0], u1 = p[1];
        uint32_t ws[8] = {u0.x, u0.y, u0.z, u0.w, u1.x, u1.y, u1.z, u1.w};
        uint32_t r = 0;
        #pragma unroll
        for (int w = 0; w < 8; w++)
            #pragma unroll
            for (int kk = 0; kk < 4; kk++)
                if ((ws[w] >> (8 * kk)) & 0xFFu) r |= 1u << (w * 4 + kk);
        g_mbits[((size_t)(b * LL + qt * 128 + row)) * (LL / 32) + kt * 4 + wc] = r;
        any |= r;
    }
    int f = __syncthreads_or(any != 0);
    if (threadIdx.x == 0) g_mflags[(b * 8 + qt) * 8 + kt] = (unsigned char)f;
}

// ---------------------------------------------------------------------------
// Weight fp32 -> fp16 convert
// ---------------------------------------------------------------------------
__global__ __launch_bounds__(256)
void split_w(const float* __restrict__ w0, const float* __restrict__ w1,
             const float* __restrict__ w2, const float* __restrict__ w3)
{
    int z = blockIdx.z;
    const float* src = (z == 0) ? w0 : (z == 1) ? w1 : (z == 2) ? w2 : w3;
    int i = blockIdx.x * blockDim.x + threadIdx.x;
    float4 f = reinterpret_cast<const float4*>(src)[i];
    uint32_t* dp = reinterpret_cast<uint32_t*>(g_w16[z]);
    dp[2*i]   = pack_h2(f.x, f.y);
    dp[2*i+1] = pack_h2(f.z, f.w);
}

// ---------------------------------------------------------------------------
// Fused Q/K/V projection GEMMs (as round 9).
// ---------------------------------------------------------------------------
#define PH      80                       // smem pitch: 64B data + 16 pad
#define TILE_B  (128 * PH)               // 10240
#define STAGE_B (2 * TILE_B)             // 20480
#define NCHUNK  (DD / 32)                // 24

__global__ __launch_bounds__(256, 2)
void qkv_gemm(const float* __restrict__ Q, const float* __restrict__ K,
              const float* __restrict__ V,
              const float* __restrict__ bq, const float* __restrict__ bk,
              const float* __restrict__ bv)
{
    extern __shared__ __align__(128) char smem[];
    const uint32_t sbase = smem_u32(smem);
    const int z = blockIdx.z;
    const int m0 = blockIdx.y * 128, n0 = blockIdx.x * 128;
    const int tid = threadIdx.x;
    const int wid = tid >> 5, lane = tid & 31;
    const int wm = wid & 3, wn = wid >> 2;

    const float* A = ((z == 0) ? Q : (z == 1) ? K : V) + (size_t)m0 * DD;
    const __half* B = g_w16[z] + (size_t)n0 * DD;
    const float* bias = (z == 0) ? bq : (z == 1) ? bk : bv;
    __half* oh = (z == 0) ? g_q16 : (z == 1) ? g_k16 : g_v16;
    const float scale = (z == 0) ? 0.125f * LOG2E : 1.0f;

    const int arow[4] = { tid >> 3, (tid + 256) >> 3, (tid + 512) >> 3, (tid + 768) >> 3 };
    const int afsg = tid & 7;

    float4 abuf[4];
    auto ldg_A = [&](int kc) {
        const float* g = A + kc * 32 + afsg * 4;
        #pragma unroll
        for (int t = 0; t < 4; t++)
            abuf[t] = *reinterpret_cast<const float4*>(g + (size_t)arow[t] * DD);
    };
    auto sts_A = [&](int st) {
        char* base = smem + st * STAGE_B;
        #pragma unroll
        for (int t = 0; t < 4; t++) {
            uint2 h;
            h.x = pack_h2(abuf[t].x, abuf[t].y);
            h.y = pack_h2(abuf[t].z, abuf[t].w);
            *reinterpret_cast<uint2*>(base + arow[t] * PH + afsg * 8) = h;
        }
    };
    auto cp_B = [&](int kc, int st) {
        #pragma unroll
        for (int t = 0; t < 2; t++) {
            int id = tid + t * 256;
            int row = id >> 2, seg = id & 3;
            cp_async16(sbase + st * STAGE_B + TILE_B + row * PH + seg * 16,
                       B + (size_t)row * DD + kc * 32 + seg * 8);
        }
        cp_commit();
    };

    float acc[2][8][4];
    #pragma unroll
    for (int i = 0; i < 2; i++)
        #pragma unroll
        for (int j = 0; j < 8; j++)
            #pragma unroll
            for (int k = 0; k < 4; k++) acc[i][j][k] = 0.f;

    ldg_A(0);
    cp_B(0, 0);

    const int lrow = lane & 15;
    const int lhalf = lane >> 4;

    #pragma unroll 1
    for (int c = 0; c < NCHUNK; c++) {
        const int s = c & 1;
        sts_A(s);
        if (c + 1 < NCHUNK) {
            ldg_A(c + 1);
            cp_B(c + 1, s ^ 1);
            cp_wait<1>();
        } else {
            cp_wait<0>();
        }
        __syncthreads();

        const uint32_t stg = sbase + s * STAGE_B;
        #pragma unroll
        for (int ks = 0; ks < 2; ks++) {
            const int seg = ks * 2 + lhalf;
            uint32_t ah[2][4];
            #pragma unroll
            for (int mf = 0; mf < 2; mf++) {
                uint32_t off = (uint32_t)((wm * 32 + mf * 16 + lrow) * PH + seg * 16);
                ldmatrix_x4(ah[mf][0], ah[mf][1], ah[mf][2], ah[mf][3], stg + off);
            }
            #pragma unroll
            for (int ng = 0; ng < 4; ng++) {
                uint32_t off = (uint32_t)((wn * 64 + ng * 16 + lrow) * PH + seg * 16);
                uint32_t b0, b1, b2, b3;
                ldmatrix_x4(b0, b1, b2, b3, stg + TILE_B + off);
                #pragma unroll
                for (int mf = 0; mf < 2; mf++) {
                    mma_f16(acc[mf][2*ng  ], ah[mf], b0, b2);
                    mma_f16(acc[mf][2*ng+1], ah[mf], b1, b3);
                }
            }
        }
        __syncthreads();
    }

    #pragma unroll
    for (int nf = 0; nf < 8; nf++) {
        const int col = n0 + wn * 64 + nf * 8 + (lane & 3) * 2;
        const float b0 = bias[col], b1 = bias[col + 1];
        #pragma unroll
        for (int mf = 0; mf < 2; mf++) {
            const int r0 = m0 + wm * 32 + mf * 16 + (lane >> 2);
            const float* a = acc[mf][nf];
            #pragma unroll
            for (int half = 0; half < 2; half++) {
                const int m = r0 + half * 8;
                uint32_t hp = pack_h2((a[2*half] + b0) * scale,
                                      (a[2*half+1] + b1) * scale);
                int bb = m >> 10, l = m & 1023;
                int hh = col >> 6, d = col & 63;
                size_t idx = (((size_t)(bb * HH + hh) << 10) + l) * DHH + d;
                *reinterpret_cast<uint32_t*>(oh + idx) = hp;
            }
        }
    }
}

// ---------------------------------------------------------------------------
// Fused attention + output projection (dataflow-synced via g_sync).
// Blocks [0, 768): attention, 128 Q rows x (h, b), KV tile 64, occ 2.
// Blocks [768, 1536): out-proj GEMM tiles 64(m) x 128(n), wait for ctx rows.
// ---------------------------------------------------------------------------
#define AROWB   144                     // 128B data + 16 pad
#define QTILE_B (128 * AROWB)           // 18432
#define KTILE_B (64 * AROWB)            // 9216
#define ASMEM   (QTILE_B + 4 * KTILE_B) // 55296
// out role layout inside the same smem window
#define OA_TILE (64 * PH)               // 5120
#define OSTAGE  (OA_TILE + 128 * PH)    // 15360 (x2 = 30720 <= ASMEM)

__global__ __launch_bounds__(256, 2)
void attn_out(const float* __restrict__ bias_o, float* __restrict__ out)
{
    extern __shared__ __align__(128) char smem[];
    const uint32_t sb = smem_u32(smem);
    const int tid = threadIdx.x, wid = tid >> 5, lane = tid & 31;

    if (blockIdx.x < 768) {
        // =================== ATTENTION ROLE ===================
        const int id = blockIdx.x;
        const int qt = id & 7, h = (id >> 3) % 12, b = id / 96;
        const int q0 = qt * 128;
        const size_t hb = ((size_t)(b * HH + h)) << 16;

        const uint32_t SQ = sb;
        auto stage = [&](int s) { return sb + QTILE_B + (uint32_t)s * 2 * KTILE_B; };

        auto load_q = [&]() {
            const __half* g = g_q16 + hb + (size_t)q0 * 64;
            #pragma unroll
            for (int it = 0; it < 4; it++) {
                int iid = tid + it * 256;
                int row = iid >> 3, seg = iid & 7;
                cp_async16(SQ + row * AROWB + seg * 16, g + (size_t)row * 64 + seg * 8);
            }
            cp_commit();
        };
        auto load_kv = [&](int t, int s) {
            const size_t off = hb + (size_t)t * 64 * 64;
            uint32_t st = stage(s);
            #pragma unroll
            for (int it = 0; it < 2; it++) {
                int iid = tid + it * 256;
                int row = iid >> 3, seg = iid & 7;
                cp_async16(st + row * AROWB + seg * 16,
                           g_k16 + off + (size_t)row * 64 + seg * 8);
                cp_async16(st + KTILE_B + row * AROWB + seg * 16,
                           g_v16 + off + (size_t)row * 64 + seg * 8);
            }
            cp_commit();
        };

        load_q();
        load_kv(0, 0);
        cp_wait<1>();
        __syncthreads();

        const int lr = lane & 15, lh = lane >> 4;
        uint32_t qf[4][4];
        #pragma unroll
        for (int ks = 0; ks < 4; ks++) {
            uint32_t off = (uint32_t)((wid * 16 + lr) * AROWB + ks * 32 + lh * 16);
            ldmatrix_x4(qf[ks][0], qf[ks][1], qf[ks][2], qf[ks][3], SQ + off);
        }

        float mA = -INFINITY, mB = -INFINITY, lA = 0.f, lB = 0.f;
        float o[8][4];
        #pragma unroll
        for (int i = 0; i < 8; i++)
            #pragma unroll
            for (int j = 0; j < 4; j++) o[i][j] = 0.f;

        const unsigned char* flagp = g_mflags + (b * 8 + qt) * 8;

        #pragma unroll 1
        for (int t = 0; t < 16; t++) {
            if (t < 15) { load_kv(t + 1, (t + 1) & 1); cp_wait<1>(); }
            else        { cp_wait<0>(); }
            __syncthreads();
            const uint32_t st = stage(t & 1);

            float s[8][4];
            #pragma unroll
            for (int j = 0; j < 8; j++)
                #pragma unroll
                for (int k = 0; k < 4; k++) s[j][k] = 0.f;

            #pragma unroll
            for (int ks = 0; ks < 4; ks++) {
                #pragma unroll
                for (int ng = 0; ng < 4; ng++) {
                    uint32_t off = (uint32_t)((ng * 16 + lr) * AROWB + ks * 32 + lh * 16);
                    uint32_t k0, k1, k2, k3;
                    ldmatrix_x4(k0, k1, k2, k3, st + off);
                    mma_f16(s[2*ng  ], qf[ks], k0, k2);
                    mma_f16(s[2*ng+1], qf[ks], k1, k3);
                }
            }

            if (flagp[t >> 1]) {
                const uint32_t* mr = g_mbits
                    + ((size_t)(b * LL + q0 + wid * 16 + (lane >> 2))) * (LL / 32) + t * 2;
                uint32_t wA[2], wB[2];
                #pragma unroll
                for (int ww = 0; ww < 2; ww++) { wA[ww] = mr[ww]; wB[ww] = mr[8 * (LL/32) + ww]; }
                #pragma unroll
                for (int j = 0; j < 8; j++) {
                    int bp = (j & 3) * 8 + (lane & 3) * 2;
                    uint32_t a = wA[j >> 2], bw = wB[j >> 2];
                    if ((a  >> bp)      & 1u) s[j][0] = -INFINITY;
                    if ((a  >> (bp+1))  & 1u) s[j][1] = -INFINITY;
                    if ((bw >> bp)      & 1u) s[j][2] = -INFINITY;
                    if ((bw >> (bp+1))  & 1u) s[j][3] = -INFINITY;
                }
            }

            float mxA = -INFINITY, mxB = -INFINITY;
            #pragma unroll
            for (int j = 0; j < 8; j++) {
                mxA = fmaxf(mxA, fmaxf(s[j][0], s[j][1]));
                mxB = fmaxf(mxB, fmaxf(s[j][2], s[j][3]));
            }
            mxA = fmaxf(mxA, __shfl_xor_sync(0xffffffffu, mxA, 1));
            mxA = fmaxf(mxA, __shfl_xor_sync(0xffffffffu, mxA, 2));
            mxB = fmaxf(mxB, __shfl_xor_sync(0xffffffffu, mxB, 1));
            mxB = fmaxf(mxB, __shfl_xor_sync(0xffffffffu, mxB, 2));
            float mnA = fmaxf(mA, mxA), mnB = fmaxf(mB, mxB);
            float aA = (mA == -INFINITY) ? 0.f : exp2f(mA - mnA);
            float aB = (mB == -INFINITY) ? 0.f : exp2f(mB - mnB);
            float subA = (mnA == -INFINITY) ? 0.f : mnA;
            float subB = (mnB == -INFINITY) ? 0.f : mnB;
            float sA = 0.f, sB = 0.f;
            #pragma unroll
            for (int j = 0; j < 8; j++) {
                s[j][0] = exp2f(s[j][0] - subA);
                s[j][1] = exp2f(s[j][1] - subA);
                s[j][2] = exp2f(s[j][2] - subB);
                s[j][3] = exp2f(s[j][3] - subB);
                sA += s[j][0] + s[j][1];
                sB += s[j][2] + s[j][3];
            }
            sA += __shfl_xor_sync(0xffffffffu, sA, 1);
            sA += __shfl_xor_sync(0xffffffffu, sA, 2);
            sB += __shfl_xor_sync(0xffffffffu, sB, 1);
            sB += __shfl_xor_sync(0xffffffffu, sB, 2);
            lA = lA * aA + sA; lB = lB * aB + sB;
            mA = mnA; mB = mnB;
            #pragma unroll
            for (int nf = 0; nf < 8; nf++) {
                o[nf][0] *= aA; o[nf][1] *= aA;
                o[nf][2] *= aB; o[nf][3] *= aB;
            }

            #pragma unroll
            for (int ks = 0; ks < 4; ks++) {
                uint32_t ap[4];
                ap[0] = pack_h2(s[2*ks  ][0], s[2*ks  ][1]);
                ap[1] = pack_h2(s[2*ks  ][2], s[2*ks  ][3]);
                ap[2] = pack_h2(s[2*ks+1][0], s[2*ks+1][1]);
                ap[3] = pack_h2(s[2*ks+1][2], s[2*ks+1][3]);
                #pragma unroll
                for (int ng = 0; ng < 4; ng++) {
                    uint32_t voff = (uint32_t)((ks * 16 + lr) * AROWB + ng * 32 + lh * 16);
                    uint32_t v0, v1, v2, v3;
                    ldmatrix_x4_t(v0, v1, v2, v3, st + KTILE_B + voff);
                    mma_f16(o[2*ng  ], ap, v0, v1);
                    mma_f16(o[2*ng+1], ap, v2, v3);
                }
            }
            __syncthreads();
        }

        float iA = (lA > 0.f) ? (1.f / lA) : 0.f;
        float iB = (lB > 0.f) ? (1.f / lB) : 0.f;
        size_t rowA = (size_t)b * LL + q0 + wid * 16 + (lane >> 2);
        size_t rowB = rowA + 8;
        #pragma unroll
        for (int nf = 0; nf < 8; nf++) {
            int col = h * 64 + nf * 8 + (lane & 3) * 2;
            *reinterpret_cast<uint32_t*>(g_c16 + rowA * DD + col)
                = pack_h2(o[nf][0] * iA, o[nf][1] * iA);
            *reinterpret_cast<uint32_t*>(g_c16 + rowB * DD + col)
                = pack_h2(o[nf][2] * iB, o[nf][3] * iB);
        }

        __syncthreads();
        if (tid == 0) {
            __threadfence();
            atomicAdd(&g_sync[b * 8 + qt], 1);
        }
    } else {
        // =================== OUT-PROJECTION ROLE ===================
        const int oid = blockIdx.x - 768;      // 768 tiles: 128 m x 6 n
        const int mt = oid & 127;
        const int nt = oid >> 7;
        const int wm = wid & 3, wn = wid >> 2;

        // Wait for all 12 heads of this 128-row q-tile to land in ctx.
        const int flag = (mt >> 4) * 8 + ((mt & 15) >> 1);
        if (tid == 0) {
            while (atomicAdd(&g_sync[flag], 0) < HH) __nanosleep(128);
        }
        __syncthreads();

        const __half* A = g_c16 + (size_t)mt * 64 * DD;
        const __half* B = g_w16[3] + (size_t)nt * 128 * DD;

        auto load_chunk = [&](int kc, int st) {
            #pragma unroll
            for (int t = 0; t < 3; t++) {
                int iid = tid + t * 256;            // 0..767
                uint32_t dst; const __half* src;
                if (iid < 256) {
                    int row = iid >> 2, seg = iid & 3;
                    dst = sb + st * OSTAGE + row * PH + seg * 16;
                    src = A + (size_t)row * DD + kc * 32 + seg * 8;
                } else {
                    int rem = iid - 256;
                    int row = rem >> 2, seg = rem & 3;
                    dst = sb + st * OSTAGE + OA_TILE + row * PH + seg * 16;
                    src = B + (size_t)row * DD + kc * 32 + seg * 8;
                }
                cp_async16(dst, src);
            }
            cp_commit();
        };

        float acc[8][4];
        #pragma unroll
        for (int j = 0; j < 8; j++)
            #pragma unroll
            for (int k = 0; k < 4; k++) acc[j][k] = 0.f;

        load_chunk(0, 0);

        const int lrow = lane & 15;
        const int lhalf = lane >> 4;

        #pragma unroll 1
        for (int c = 0; c < NCHUNK; c++) {
            const int s = c & 1;
            if (c + 1 < NCHUNK) { load_chunk(c + 1, s ^ 1); cp_wait<1>(); }
            else                { cp_wait<0>(); }
            __syncthreads();

            const uint32_t stg = sb + s * OSTAGE;
            #pragma unroll
            for (int ks = 0; ks < 2; ks++) {
                const int seg = ks * 2 + lhalf;
                uint32_t ah[4];
                uint32_t aoff = (uint32_t)((wm * 16 + lrow) * PH + seg * 16);
                ldmatrix_x4(ah[0], ah[1], ah[2], ah[3], stg + aoff);
                #pragma unroll
                for (int ng = 0; ng < 4; ng++) {
                    uint32_t boff = (uint32_t)((wn * 64 + ng * 16 + lrow) * PH + seg * 16);
                    uint32_t b0, b1, b2, b3;
                    ldmatrix_x4(b0, b1, b2, b3, stg + OA_TILE + boff);
                    mma_f16(acc[2*ng  ], ah, b0, b2);
                    mma_f16(acc[2*ng+1], ah, b1, b3);
                }
            }
            __syncthreads();
        }

        #pragma unroll
        for (int nf = 0; nf < 8; nf++) {
            const int col = nt * 128 + wn * 64 + nf * 8 + (lane & 3) * 2;
            const float b0 = bias_o[col], b1 = bias_o[col + 1];
            const int r0 = mt * 64 + wm * 16 + (lane >> 2);
            #pragma unroll
            for (int half = 0; half < 2; half++) {
                const int m = r0 + half * 8;
                *reinterpret_cast<float2*>(out + (size_t)m * DD + col)
                    = make_float2(acc[nf][2*half] + b0, acc[nf][2*half+1] + b1);
            }
        }
    }
}

// ---------------------------------------------------------------------------
extern "C" void kernel_launch(void* const* d_in, const int* in_sizes, int n_in,
                              void* d_out, int out_size)
{
    const float* Query = (const float*)d_in[0];
    const float* Key   = (const float*)d_in[1];
    const float* Value = (const float*)d_in[2];
    const unsigned char* maskp = (const unsigned char*)d_in[3];
    const float* WQ_b = (const float*)d_in[5];
    const float* WK_b = (const float*)d_in[7];
    const float* WV_b = (const float*)d_in[9];
    const float* WO_b = (const float*)d_in[11];
    float* out = (float*)d_out;

    cudaFuncSetAttribute(qkv_gemm, cudaFuncAttributeMaxDynamicSharedMemorySize,
                         2 * STAGE_B);
    cudaFuncSetAttribute(attn_out, cudaFuncAttributeMaxDynamicSharedMemorySize,
                         ASMEM);

    // Mask pack + flags + g_sync reset
    prep_mask<<<dim3(8, 8, 8), 256>>>(maskp);

    // Weight converts
    split_w<<<dim3(DD * DD / 4 / 256, 1, 4), 256>>>(
        (const float*)d_in[4], (const float*)d_in[6],
        (const float*)d_in[8], (const float*)d_in[10]);

    // Fused Q/K/V projections (fp32 A converted in-kernel)
    qkv_gemm<<<dim3(DD / 128, MM / 128, 3), 256, 2 * STAGE_B>>>(
        Query, Key, Value, WQ_b, WK_b, WV_b);

    // Fused attention + output projection
    attn_out<<<1536, 256, ASMEM>>>(WO_b, out);
}

// round 11
// speedup vs baseline: 2.9470x; 1.0462x over previous
#include <cuda_runtime.h>
#include <cuda_fp16.h>
#include <cstdint>

// Problem constants
#define BB 8
#define LL 1024
#define DD 768
#define HH 12
#define DHH 64
#define MM (BB*LL)   // 8192
#define LOG2E 1.4426950408889634f

// ---------------------------------------------------------------------------
// Scratch (device globals — no allocation allowed)
// ---------------------------------------------------------------------------
__device__ __half g_q16[BB*HH*LL*DHH];     // [B,H,L,Dh], pre-scaled by log2e/8
__device__ __half g_k16[BB*HH*LL*DHH];
__device__ __half g_v16[BB*HH*LL*DHH];
__device__ __half g_c16[MM*DD];            // attention context [M, D]
__device__ __half g_w16[4][DD*DD];         // fp16 weights
__device__ uint32_t g_mbits[BB*LL*(LL/32)];
__device__ unsigned char g_mflags[BB*8*8];
__device__ int g_sync[BB*8];               // attn->out: per (b, qtile128), target 12
__device__ int g_qkv[3*BB*6];              // qkv->attn: per (z, b, ntile), target 8

// ---------------------------------------------------------------------------
// PTX helpers — baseline (non-'a') features only
// ---------------------------------------------------------------------------
__device__ __forceinline__ uint32_t smem_u32(const void* p) {
    uint32_t a;
    asm("{ .reg .u64 t; cvta.to.shared.u64 t, %1; cvt.u32.u64 %0, t; }"
        : "=r"(a) : "l"(p));
    return a;
}
__device__ __forceinline__ void cp_async16(uint32_t saddr, const void* gptr) {
    asm volatile("cp.async.cg.shared.global [%0], [%1], 16;"
                 :: "r"(saddr), "l"(gptr) : "memory");
}
__device__ __forceinline__ void cp_commit() {
    asm volatile("cp.async.commit_group;" ::: "memory");
}
template<int N>
__device__ __forceinline__ void cp_wait() {
    asm volatile("cp.async.wait_group %0;" :: "n"(N) : "memory");
}
__device__ __forceinline__ void ldmatrix_x4(uint32_t& r0, uint32_t& r1,
                                            uint32_t& r2, uint32_t& r3,
                                            uint32_t addr) {
    asm volatile("ldmatrix.sync.aligned.m8n8.x4.shared.b16 {%0,%1,%2,%3}, [%4];"
                 : "=r"(r0), "=r"(r1), "=r"(r2), "=r"(r3) : "r"(addr));
}
__device__ __forceinline__ void ldmatrix_x4_t(uint32_t& r0, uint32_t& r1,
                                              uint32_t& r2, uint32_t& r3,
                                              uint32_t addr) {
    asm volatile("ldmatrix.sync.aligned.m8n8.x4.trans.shared.b16 {%0,%1,%2,%3}, [%4];"
                 : "=r"(r0), "=r"(r1), "=r"(r2), "=r"(r3) : "r"(addr));
}
__device__ __forceinline__ void mma_f16(float* c, const uint32_t* a,
                                        uint32_t b0, uint32_t b1) {
    asm volatile(
        "mma.sync.aligned.m16n8k16.row.col.f32.f16.f16.f32 "
        "{%0,%1,%2,%3}, {%4,%5,%6,%7}, {%8,%9}, {%0,%1,%2,%3};"
        : "+f"(c[0]), "+f"(c[1]), "+f"(c[2]), "+f"(c[3])
        : "r"(a[0]), "r"(a[1]), "r"(a[2]), "r"(a[3]), "r"(b0), "r"(b1));
}
__device__ __forceinline__ uint32_t pack_h2(float a, float b) {
    __half2 h = __floats2half2_rn(a, b);
    return *reinterpret_cast<uint32_t*>(&h);
}

// ---------------------------------------------------------------------------
// Mask preprocessing — pack bits + per-tile flag; resets sync counters.
// ---------------------------------------------------------------------------
__global__ __launch_bounds__(256)
void prep_mask(const unsigned char* __restrict__ mask)
{
    const int kt = blockIdx.x, qt = blockIdx.y, b = blockIdx.z;
    if (kt == 0 && threadIdx.x == 0) g_sync[b * 8 + qt] = 0;
    if (kt == 0 && qt == 0 && b == 0 && threadIdx.x < 3 * BB * 6)
        g_qkv[threadIdx.x] = 0;
    uint32_t any = 0;
    #pragma unroll
    for (int k = 0; k < 2; k++) {
        int widx = threadIdx.x * 2 + k;      // 0..511
        int row  = widx >> 2;                // 0..127
        int wc   = widx & 3;
        const uint4* p = reinterpret_cast<const uint4*>(
            mask + ((size_t)(b * LL + qt * 128 + row)) * LL + kt * 128 + wc * 32);
        uint4 u0 = p[0], u1 = p[1];
        uint32_t ws[8] = {u0.x, u0.y, u0.z, u0.w, u1.x, u1.y, u1.z, u1.w};
        uint32_t r = 0;
        #pragma unroll
        for (int w = 0; w < 8; w++)
            #pragma unroll
            for (int kk = 0; kk < 4; kk++)
                if ((ws[w] >> (8 * kk)) & 0xFFu) r |= 1u << (w * 4 + kk);
        g_mbits[((size_t)(b * LL + qt * 128 + row)) * (LL / 32) + kt * 4 + wc] = r;
        any |= r;
    }
    int f = __syncthreads_or(any != 0);
    if (threadIdx.x == 0) g_mflags[(b * 8 + qt) * 8 + kt] = (unsigned char)f;
}

// ---------------------------------------------------------------------------
// Weight fp32 -> fp16 convert
// ---------------------------------------------------------------------------
__global__ __launch_bounds__(256)
void split_w(const float* __restrict__ w0, const float* __restrict__ w1,
             const float* __restrict__ w2, const float* __restrict__ w3)
{
    int z = blockIdx.z;
    const float* src = (z == 0) ? w0 : (z == 1) ? w1 : (z == 2) ? w2 : w3;
    int i = blockIdx.x * blockDim.x + threadIdx.x;
    float4 f = reinterpret_cast<const float4*>(src)[i];
    uint32_t* dp = reinterpret_cast<uint32_t*>(g_w16[z]);
    dp[2*i]   = pack_h2(f.x, f.y);
    dp[2*i+1] = pack_h2(f.z, f.w);
}

// ---------------------------------------------------------------------------
// Mega kernel: qkv-proj [0,1152) -> attention [1152,1920) -> out-proj [1920,2688)
// with dataflow sync via g_qkv / g_sync. Dependencies always point to lower
// blockIdx -> queue-ordered dispatch cannot deadlock.
// ---------------------------------------------------------------------------
#define PH      80                       // GEMM smem pitch (64B data + 16 pad)
#define TILE_B  (128 * PH)               // 10240
#define STAGE_B (2 * TILE_B)             // 20480
#define NCHUNK  (DD / 32)                // 24

#define AROWB   144                     // attention pitch (128B data + 16 pad)
#define QTILE_B (128 * AROWB)           // 18432
#define KTILE_B (64 * AROWB)            // 9216
#define ASMEM   (QTILE_B + 4 * KTILE_B) // 55296
#define OA_TILE (64 * PH)               // 5120
#define OSTAGE  (OA_TILE + 128 * PH)    // 15360

__global__ __launch_bounds__(256, 2)
void mha_mega(const float* __restrict__ Q, const float* __restrict__ K,
              const float* __restrict__ V,
              const float* __restrict__ bq, const float* __restrict__ bk,
              const float* __restrict__ bv,
              const float* __restrict__ bias_o, float* __restrict__ out)
{
    extern __shared__ __align__(128) char smem[];
    const uint32_t sb = smem_u32(smem);
    const int tid = threadIdx.x, wid = tid >> 5, lane = tid & 31;

    if (blockIdx.x < 1152) {
        // =================== QKV PROJECTION ROLE ===================
        const int id = blockIdx.x;
        const int z  = id / 384;             // 0: Q, 1: K, 2: V
        const int rem = id % 384;
        const int nx = rem % 6, my = rem / 6;
        const int m0 = my * 128, n0 = nx * 128;
        const int wm = wid & 3, wn = wid >> 2;

        const float* A = ((z == 0) ? Q : (z == 1) ? K : V) + (size_t)m0 * DD;
        const __half* B = g_w16[z] + (size_t)n0 * DD;
        const float* bias = (z == 0) ? bq : (z == 1) ? bk : bv;
        __half* oh = (z == 0) ? g_q16 : (z == 1) ? g_k16 : g_v16;
        const float scale = (z == 0) ? 0.125f * LOG2E : 1.0f;

        const int arow[4] = { tid >> 3, (tid + 256) >> 3,
                              (tid + 512) >> 3, (tid + 768) >> 3 };
        const int afsg = tid & 7;

        float4 abuf[4];
        auto ldg_A = [&](int kc) {
            const float* g = A + kc * 32 + afsg * 4;
            #pragma unroll
            for (int t = 0; t < 4; t++)
                abuf[t] = *reinterpret_cast<const float4*>(g + (size_t)arow[t] * DD);
        };
        auto sts_A = [&](int st) {
            char* base = smem + st * STAGE_B;
            #pragma unroll
            for (int t = 0; t < 4; t++) {
                uint2 h;
                h.x = pack_h2(abuf[t].x, abuf[t].y);
                h.y = pack_h2(abuf[t].z, abuf[t].w);
                *reinterpret_cast<uint2*>(base + arow[t] * PH + afsg * 8) = h;
            }
        };
        auto cp_B = [&](int kc, int st) {
            #pragma unroll
            for (int t = 0; t < 2; t++) {
                int iid = tid + t * 256;
                int row = iid >> 2, seg = iid & 3;
                cp_async16(sb + st * STAGE_B + TILE_B + row * PH + seg * 16,
                           B + (size_t)row * DD + kc * 32 + seg * 8);
            }
            cp_commit();
        };

        float acc[2][8][4];
        #pragma unroll
        for (int i = 0; i < 2; i++)
            #pragma unroll
            for (int j = 0; j < 8; j++)
                #pragma unroll
                for (int k = 0; k < 4; k++) acc[i][j][k] = 0.f;

        ldg_A(0);
        cp_B(0, 0);

        const int lrow = lane & 15;
        const int lhalf = lane >> 4;

        #pragma unroll 1
        for (int c = 0; c < NCHUNK; c++) {
            const int s = c & 1;
            sts_A(s);
            if (c + 1 < NCHUNK) {
                ldg_A(c + 1);
                cp_B(c + 1, s ^ 1);
                cp_wait<1>();
            } else {
                cp_wait<0>();
            }
            __syncthreads();

            const uint32_t stg = sb + s * STAGE_B;
            #pragma unroll
            for (int ks = 0; ks < 2; ks++) {
                const int seg = ks * 2 + lhalf;
                uint32_t ah[2][4];
                #pragma unroll
                for (int mf = 0; mf < 2; mf++) {
                    uint32_t off = (uint32_t)((wm * 32 + mf * 16 + lrow) * PH + seg * 16);
                    ldmatrix_x4(ah[mf][0], ah[mf][1], ah[mf][2], ah[mf][3], stg + off);
                }
                #pragma unroll
                for (int ng = 0; ng < 4; ng++) {
                    uint32_t off = (uint32_t)((wn * 64 + ng * 16 + lrow) * PH + seg * 16);
                    uint32_t b0, b1, b2, b3;
                    ldmatrix_x4(b0, b1, b2, b3, stg + TILE_B + off);
                    #pragma unroll
                    for (int mf = 0; mf < 2; mf++) {
                        mma_f16(acc[mf][2*ng  ], ah[mf], b0, b2);
                        mma_f16(acc[mf][2*ng+1], ah[mf], b1, b3);
                    }
                }
            }
            __syncthreads();
        }

        #pragma unroll
        for (int nf = 0; nf < 8; nf++) {
            const int col = n0 + wn * 64 + nf * 8 + (lane & 3) * 2;
            const float b0 = bias[col], b1 = bias[col + 1];
            #pragma unroll
            for (int mf = 0; mf < 2; mf++) {
                const int r0 = m0 + wm * 32 + mf * 16 + (lane >> 2);
                const float* a = acc[mf][nf];
                #pragma unroll
                for (int half = 0; half < 2; half++) {
                    const int m = r0 + half * 8;
                    uint32_t hp = pack_h2((a[2*half] + b0) * scale,
                                          (a[2*half+1] + b1) * scale);
                    int bb = m >> 10, l = m & 1023;
                    int hh = col >> 6, d = col & 63;
                    size_t idx = (((size_t)(bb * HH + hh) << 10) + l) * DHH + d;
                    *reinterpret_cast<uint32_t*>(oh + idx) = hp;
                }
            }
        }

        __syncthreads();
        if (tid == 0) {
            __threadfence();
            atomicAdd(&g_qkv[z * 48 + (my >> 3) * 6 + nx], 1);
        }

    } else if (blockIdx.x < 1920) {
        // =================== ATTENTION ROLE ===================
        const int id = blockIdx.x - 1152;
        const int qt = id & 7, h = (id >> 3) % 12, b = id / 96;
        const int q0 = qt * 128;
        const size_t hb = ((size_t)(b * HH + h)) << 16;

        // Wait for Q/K/V of this (b, head-pair) to be projected.
        if (tid == 0) {
            const int nt = h >> 1;
            int i0 = 0 * 48 + b * 6 + nt;
            int i1 = 1 * 48 + b * 6 + nt;
            int i2 = 2 * 48 + b * 6 + nt;
            while (atomicAdd(&g_qkv[i0], 0) < 8 ||
                   atomicAdd(&g_qkv[i1], 0) < 8 ||
                   atomicAdd(&g_qkv[i2], 0) < 8) __nanosleep(128);
            __threadfence();
        }
        __syncthreads();

        const uint32_t SQ = sb;
        auto stage = [&](int s) { return sb + QTILE_B + (uint32_t)s * 2 * KTILE_B; };

        auto load_q = [&]() {
            const __half* g = g_q16 + hb + (size_t)q0 * 64;
            #pragma unroll
            for (int it = 0; it < 4; it++) {
                int iid = tid + it * 256;
                int row = iid >> 3, seg = iid & 7;
                cp_async16(SQ + row * AROWB + seg * 16, g + (size_t)row * 64 + seg * 8);
            }
            cp_commit();
        };
        auto load_kv = [&](int t, int s) {
            const size_t off = hb + (size_t)t * 64 * 64;
            uint32_t st = stage(s);
            #pragma unroll
            for (int it = 0; it < 2; it++) {
                int iid = tid + it * 256;
                int row = iid >> 3, seg = iid & 7;
                cp_async16(st + row * AROWB + seg * 16,
                           g_k16 + off + (size_t)row * 64 + seg * 8);
                cp_async16(st + KTILE_B + row * AROWB + seg * 16,
                           g_v16 + off + (size_t)row * 64 + seg * 8);
            }
            cp_commit();
        };

        load_q();
        load_kv(0, 0);
        cp_wait<1>();
        __syncthreads();

        const int lr = lane & 15, lh = lane >> 4;
        uint32_t qf[4][4];
        #pragma unroll
        for (int ks = 0; ks < 4; ks++) {
            uint32_t off = (uint32_t)((wid * 16 + lr) * AROWB + ks * 32 + lh * 16);
            ldmatrix_x4(qf[ks][0], qf[ks][1], qf[ks][2], qf[ks][3], SQ + off);
        }

        float mA = -INFINITY, mB = -INFINITY, lA = 0.f, lB = 0.f;
        float o[8][4];
        #pragma unroll
        for (int i = 0; i < 8; i++)
            #pragma unroll
            for (int j = 0; j < 4; j++) o[i][j] = 0.f;

        const unsigned char* flagp = g_mflags + (b * 8 + qt) * 8;

        #pragma unroll 1
        for (int t = 0; t < 16; t++) {
            if (t < 15) { load_kv(t + 1, (t + 1) & 1); cp_wait<1>(); }
            else        { cp_wait<0>(); }
            __syncthreads();
            const uint32_t st = stage(t & 1);

            float s[8][4];
            #pragma unroll
            for (int j = 0; j < 8; j++)
                #pragma unroll
                for (int k = 0; k < 4; k++) s[j][k] = 0.f;

            #pragma unroll
            for (int ks = 0; ks < 4; ks++) {
                #pragma unroll
                for (int ng = 0; ng < 4; ng++) {
                    uint32_t off = (uint32_t)((ng * 16 + lr) * AROWB + ks * 32 + lh * 16);
                    uint32_t k0, k1, k2, k3;
                    ldmatrix_x4(k0, k1, k2, k3, st + off);
                    mma_f16(s[2*ng  ], qf[ks], k0, k2);
                    mma_f16(s[2*ng+1], qf[ks], k1, k3);
                }
            }

            if (flagp[t >> 1]) {
                const uint32_t* mr = g_mbits
                    + ((size_t)(b * LL + q0 + wid * 16 + (lane >> 2))) * (LL / 32) + t * 2;
                uint32_t wA[2], wB[2];
                #pragma unroll
                for (int ww = 0; ww < 2; ww++) { wA[ww] = mr[ww]; wB[ww] = mr[8 * (LL/32) + ww]; }
                #pragma unroll
                for (int j = 0; j < 8; j++) {
                    int bp = (j & 3) * 8 + (lane & 3) * 2;
                    uint32_t a = wA[j >> 2], bw = wB[j >> 2];
                    if ((a  >> bp)      & 1u) s[j][0] = -INFINITY;
                    if ((a  >> (bp+1))  & 1u) s[j][1] = -INFINITY;
                    if ((bw >> bp)      & 1u) s[j][2] = -INFINITY;
                    if ((bw >> (bp+1))  & 1u) s[j][3] = -INFINITY;
                }
            }

            float mxA = -INFINITY, mxB = -INFINITY;
            #pragma unroll
            for (int j = 0; j < 8; j++) {
                mxA = fmaxf(mxA, fmaxf(s[j][0], s[j][1]));
                mxB = fmaxf(mxB, fmaxf(s[j][2], s[j][3]));
            }
            mxA = fmaxf(mxA, __shfl_xor_sync(0xffffffffu, mxA, 1));
            mxA = fmaxf(mxA, __shfl_xor_sync(0xffffffffu, mxA, 2));
            mxB = fmaxf(mxB, __shfl_xor_sync(0xffffffffu, mxB, 1));
            mxB = fmaxf(mxB, __shfl_xor_sync(0xffffffffu, mxB, 2));
            float mnA = fmaxf(mA, mxA), mnB = fmaxf(mB, mxB);
            float aA = (mA == -INFINITY) ? 0.f : exp2f(mA - mnA);
            float aB = (mB == -INFINITY) ? 0.f : exp2f(mB - mnB);
            float subA = (mnA == -INFINITY) ? 0.f : mnA;
            float subB = (mnB == -INFINITY) ? 0.f : mnB;
            float sA = 0.f, sB = 0.f;
            #pragma unroll
            for (int j = 0; j < 8; j++) {
                s[j][0] = exp2f(s[j][0] - subA);
                s[j][1] = exp2f(s[j][1] - subA);
                s[j][2] = exp2f(s[j][2] - subB);
                s[j][3] = exp2f(s[j][3] - subB);
                sA += s[j][0] + s[j][1];
                sB += s[j][2] + s[j][3];
            }
            sA += __shfl_xor_sync(0xffffffffu, sA, 1);
            sA += __shfl_xor_sync(0xffffffffu, sA, 2);
            sB += __shfl_xor_sync(0xffffffffu, sB, 1);
            sB += __shfl_xor_sync(0xffffffffu, sB, 2);
            lA = lA * aA + sA; lB = lB * aB + sB;
            mA = mnA; mB = mnB;
            if (aA != 1.f || aB != 1.f) {
                #pragma unroll
                for (int nf = 0; nf < 8; nf++) {
                    o[nf][0] *= aA; o[nf][1] *= aA;
                    o[nf][2] *= aB; o[nf][3] *= aB;
                }
            }

            #pragma unroll
            for (int ks = 0; ks < 4; ks++) {
                uint32_t ap[4];
                ap[0] = pack_h2(s[2*ks  ][0], s[2*ks  ][1]);
                ap[1] = pack_h2(s[2*ks  ][2], s[2*ks  ][3]);
                ap[2] = pack_h2(s[2*ks+1][0], s[2*ks+1][1]);
                ap[3] = pack_h2(s[2*ks+1][2], s[2*ks+1][3]);
                #pragma unroll
                for (int ng = 0; ng < 4; ng++) {
                    uint32_t voff = (uint32_t)((ks * 16 + lr) * AROWB + ng * 32 + lh * 16);
                    uint32_t v0, v1, v2, v3;
                    ldmatrix_x4_t(v0, v1, v2, v3, st + KTILE_B + voff);
                    mma_f16(o[2*ng  ], ap, v0, v1);
                    mma_f16(o[2*ng+1], ap, v2, v3);
                }
            }
            __syncthreads();
        }

        float iA = (lA > 0.f) ? (1.f / lA) : 0.f;
        float iB = (lB > 0.f) ? (1.f / lB) : 0.f;
        size_t rowA = (size_t)b * LL + q0 + wid * 16 + (lane >> 2);
        size_t rowB = rowA + 8;
        #pragma unroll
        for (int nf = 0; nf < 8; nf++) {
            int col = h * 64 + nf * 8 + (lane & 3) * 2;
            *reinterpret_cast<uint32_t*>(g_c16 + rowA * DD + col)
                = pack_h2(o[nf][0] * iA, o[nf][1] * iA);
            *reinterpret_cast<uint32_t*>(g_c16 + rowB * DD + col)
                = pack_h2(o[nf][2] * iB, o[nf][3] * iB);
        }

        __syncthreads();
        if (tid == 0) {
            __threadfence();
            atomicAdd(&g_sync[b * 8 + qt], 1);
        }
    } else {
        // =================== OUT-PROJECTION ROLE ===================
        const int oid = blockIdx.x - 1920;     // 768 tiles: 128 m x 6 n
        const int mt = oid & 127;
        const int nt = oid >> 7;
        const int wm = wid & 3, wn = wid >> 2;

        const int flag = (mt >> 4) * 8 + ((mt & 15) >> 1);
        if (tid == 0) {
            while (atomicAdd(&g_sync[flag], 0) < HH) __nanosleep(128);
            __threadfence();
        }
        __syncthreads();

        const __half* A = g_c16 + (size_t)mt * 64 * DD;
        const __half* B = g_w16[3] + (size_t)nt * 128 * DD;

        auto load_chunk = [&](int kc, int st) {
            #pragma unroll
            for (int t = 0; t < 3; t++) {
                int iid = tid + t * 256;            // 0..767
                uint32_t dst; const __half* src;
                if (iid < 256) {
                    int row = iid >> 2, seg = iid & 3;
                    dst = sb + st * OSTAGE + row * PH + seg * 16;
                    src = A + (size_t)row * DD + kc * 32 + seg * 8;
                } else {
                    int rem = iid - 256;
                    int row = rem >> 2, seg = rem & 3;
                    dst = sb + st * OSTAGE + OA_TILE + row * PH + seg * 16;
                    src = B + (size_t)row * DD + kc * 32 + seg * 8;
                }
                cp_async16(dst, src);
            }
            cp_commit();
        };

        float acc[8][4];
        #pragma unroll
        for (int j = 0; j < 8; j++)
            #pragma unroll
            for (int k = 0; k < 4; k++) acc[j][k] = 0.f;

        load_chunk(0, 0);

        const int lrow = lane & 15;
        const int lhalf = lane >> 4;

        #pragma unroll 1
        for (int c = 0; c < NCHUNK; c++) {
            const int s = c & 1;
            if (c + 1 < NCHUNK) { load_chunk(c + 1, s ^ 1); cp_wait<1>(); }
            else                { cp_wait<0>(); }
            __syncthreads();

            const uint32_t stg = sb + s * OSTAGE;
            #pragma unroll
            for (int ks = 0; ks < 2; ks++) {
                const int seg = ks * 2 + lhalf;
                uint32_t ah[4];
                uint32_t aoff = (uint32_t)((wm * 16 + lrow) * PH + seg * 16);
                ldmatrix_x4(ah[0], ah[1], ah[2], ah[3], stg + aoff);
                #pragma unroll
                for (int ng = 0; ng < 4; ng++) {
                    uint32_t boff = (uint32_t)((wn * 64 + ng * 16 + lrow) * PH + seg * 16);
                    uint32_t b0, b1, b2, b3;
                    ldmatrix_x4(b0, b1, b2, b3, stg + OA_TILE + boff);
                    mma_f16(acc[2*ng  ], ah, b0, b2);
                    mma_f16(acc[2*ng+1], ah, b1, b3);
                }
            }
            __syncthreads();
        }

        #pragma unroll
        for (int nf = 0; nf < 8; nf++) {
            const int col = nt * 128 + wn * 64 + nf * 8 + (lane & 3) * 2;
            const float b0 = bias_o[col], b1 = bias_o[col + 1];
            const int r0 = mt * 64 + wm * 16 + (lane >> 2);
            #pragma unroll
            for (int half = 0; half < 2; half++) {
                const int m = r0 + half * 8;
                *reinterpret_cast<float2*>(out + (size_t)m * DD + col)
                    = make_float2(acc[nf][2*half] + b0, acc[nf][2*half+1] + b1);
            }
        }
    }
}

// ---------------------------------------------------------------------------
extern "C" void kernel_launch(void* const* d_in, const int* in_sizes, int n_in,
                              void* d_out, int out_size)
{
    const float* Query = (const float*)d_in[0];
    const float* Key   = (const float*)d_in[1];
    const float* Value = (const float*)d_in[2];
    const unsigned char* maskp = (const unsigned char*)d_in[3];
    const float* WQ_b = (const float*)d_in[5];
    const float* WK_b = (const float*)d_in[7];
    const float* WV_b = (const float*)d_in[9];
    const float* WO_b = (const float*)d_in[11];
    float* out = (float*)d_out;

    cudaFuncSetAttribute(mha_mega, cudaFuncAttributeMaxDynamicSharedMemorySize,
                         ASMEM);

    // Mask pack + flags + counter reset
    prep_mask<<<dim3(8, 8, 8), 256>>>(maskp);

    // Weight converts (must precede mega kernel)
    split_w<<<dim3(DD * DD / 4 / 256, 1, 4), 256>>>(
        (const float*)d_in[4], (const float*)d_in[6],
        (const float*)d_in[8], (const float*)d_in[10]);

    // Everything else: one launch
    mha_mega<<<2688, 256, ASMEM>>>(Query, Key, Value,
                                   WQ_b, WK_b, WV_b, WO_b, out);
}

// round 12
// speedup vs baseline: 2.9729x; 1.0088x over previous
#include <cuda_runtime.h>
#include <cuda_fp16.h>
#include <cstdint>

// Problem constants
#define BB 8
#define LL 1024
#define DD 768
#define HH 12
#define DHH 64
#define MM (BB*LL)   // 8192
#define LOG2E 1.4426950408889634f

// ---------------------------------------------------------------------------
// Scratch (device globals — no allocation allowed)
// ---------------------------------------------------------------------------
__device__ __half g_q16[BB*HH*LL*DHH];     // [B,H,L,Dh], pre-scaled by log2e/8
__device__ __half g_k16[BB*HH*LL*DHH];
__device__ __half g_v16[BB*HH*LL*DHH];
__device__ __half g_c16[MM*DD];            // attention context [M, D]
__device__ __half g_w16[4][DD*DD];         // fp16 weights
__device__ uint32_t g_mbits[BB*LL*(LL/32)];
__device__ unsigned char g_mflags[BB*8*8];
__device__ int g_sync[BB*8];               // attn->out: per (b, qtile128), target 12
__device__ int g_qkv[BB*6*3];              // qkv->attn: per (b, ntile, z), target 8

// ---------------------------------------------------------------------------
// PTX helpers — baseline (non-'a') features only
// ---------------------------------------------------------------------------
__device__ __forceinline__ uint32_t smem_u32(const void* p) {
    uint32_t a;
    asm("{ .reg .u64 t; cvta.to.shared.u64 t, %1; cvt.u32.u64 %0, t; }"
        : "=r"(a) : "l"(p));
    return a;
}
__device__ __forceinline__ void cp_async16(uint32_t saddr, const void* gptr) {
    asm volatile("cp.async.cg.shared.global [%0], [%1], 16;"
                 :: "r"(saddr), "l"(gptr) : "memory");
}
__device__ __forceinline__ void cp_commit() {
    asm volatile("cp.async.commit_group;" ::: "memory");
}
template<int N>
__device__ __forceinline__ void cp_wait() {
    asm volatile("cp.async.wait_group %0;" :: "n"(N) : "memory");
}
__device__ __forceinline__ void ldmatrix_x4(uint32_t& r0, uint32_t& r1,
                                            uint32_t& r2, uint32_t& r3,
                                            uint32_t addr) {
    asm volatile("ldmatrix.sync.aligned.m8n8.x4.shared.b16 {%0,%1,%2,%3}, [%4];"
                 : "=r"(r0), "=r"(r1), "=r"(r2), "=r"(r3) : "r"(addr));
}
__device__ __forceinline__ void ldmatrix_x4_t(uint32_t& r0, uint32_t& r1,
                                              uint32_t& r2, uint32_t& r3,
                                              uint32_t addr) {
    asm volatile("ldmatrix.sync.aligned.m8n8.x4.trans.shared.b16 {%0,%1,%2,%3}, [%4];"
                 : "=r"(r0), "=r"(r1), "=r"(r2), "=r"(r3) : "r"(addr));
}
__device__ __forceinline__ void mma_f16(float* c, const uint32_t* a,
                                        uint32_t b0, uint32_t b1) {
    asm volatile(
        "mma.sync.aligned.m16n8k16.row.col.f32.f16.f16.f32 "
        "{%0,%1,%2,%3}, {%4,%5,%6,%7}, {%8,%9}, {%0,%1,%2,%3};"
        : "+f"(c[0]), "+f"(c[1]), "+f"(c[2]), "+f"(c[3])
        : "r"(a[0]), "r"(a[1]), "r"(a[2]), "r"(a[3]), "r"(b0), "r"(b1));
}
__device__ __forceinline__ uint32_t pack_h2(float a, float b) {
    __half2 h = __floats2half2_rn(a, b);
    return *reinterpret_cast<uint32_t*>(&h);
}

// ---------------------------------------------------------------------------
// Prep kernel (fused): blocks [0,512) pack mask bits + per-tile flags and
// reset sync counters; blocks [512, 2816) convert weights fp32->fp16.
// ---------------------------------------------------------------------------
__global__ __launch_bounds__(256)
void prep_all(const unsigned char* __restrict__ mask,
              const float* __restrict__ w0, const float* __restrict__ w1,
              const float* __restrict__ w2, const float* __restrict__ w3)
{
    if (blockIdx.x < 512) {
        const int kt = blockIdx.x & 7, qt = (blockIdx.x >> 3) & 7, b = blockIdx.x >> 6;
        if (kt == 0 && threadIdx.x == 0) g_sync[b * 8 + qt] = 0;
        if (blockIdx.x == 0 && threadIdx.x < BB * 6 * 3) g_qkv[threadIdx.x] = 0;
        uint32_t any = 0;
        #pragma unroll
        for (int k = 0; k < 2; k++) {
            int widx = threadIdx.x * 2 + k;      // 0..511
            int row  = widx >> 2;                // 0..127
            int wc   = widx & 3;
            const uint4* p = reinterpret_cast<const uint4*>(
                mask + ((size_t)(b * LL + qt * 128 + row)) * LL + kt * 128 + wc * 32);
            uint4 u0 = p[0], u1 = p[1];
            uint32_t ws[8] = {u0.x, u0.y, u0.z, u0.w, u1.x, u1.y, u1.z, u1.w};
            uint32_t r = 0;
            #pragma unroll
            for (int w = 0; w < 8; w++)
                #pragma unroll
                for (int kk = 0; kk < 4; kk++)
                    if ((ws[w] >> (8 * kk)) & 0xFFu) r |= 1u << (w * 4 + kk);
            g_mbits[((size_t)(b * LL + qt * 128 + row)) * (LL / 32) + kt * 4 + wc] = r;
            any |= r;
        }
        int f = __syncthreads_or(any != 0);
        if (threadIdx.x == 0) g_mflags[(b * 8 + qt) * 8 + kt] = (unsigned char)f;
    } else {
        const int id = blockIdx.x - 512;         // 0..2303
        const int z = id / 576;
        const float* src = (z == 0) ? w0 : (z == 1) ? w1 : (z == 2) ? w2 : w3;
        int i = (id % 576) * 256 + threadIdx.x;
        float4 f = reinterpret_cast<const float4*>(src)[i];
        uint32_t* dp = reinterpret_cast<uint32_t*>(g_w16[z]);
        dp[2*i]   = pack_h2(f.x, f.y);
        dp[2*i+1] = pack_h2(f.z, f.w);
    }
}

// ---------------------------------------------------------------------------
// Mega kernel: qkv-proj [0,1152) -> attention [1152,1920) -> out-proj [1920,2688)
// qkv blocks ordered (b, nt, mloc, z) so attention deps complete early.
// ---------------------------------------------------------------------------
#define PH      80                       // GEMM smem pitch (64B data + 16 pad)
#define TILE_B  (128 * PH)               // 10240
#define STAGE_B (2 * TILE_B)             // 20480
#define NCHUNK  (DD / 32)                // 24

#define AROWB   144                     // attention pitch (128B data + 16 pad)
#define QTILE_B (128 * AROWB)           // 18432
#define KTILE_B (64 * AROWB)            // 9216
#define ASMEM   (QTILE_B + 4 * KTILE_B) // 55296
#define OA_TILE (64 * PH)               // 5120
#define OSTAGE  (OA_TILE + 128 * PH)    // 15360

__global__ __launch_bounds__(256, 2)
void mha_mega(const float* __restrict__ Q, const float* __restrict__ K,
              const float* __restrict__ V,
              const float* __restrict__ bq, const float* __restrict__ bk,
              const float* __restrict__ bv,
              const float* __restrict__ bias_o, float* __restrict__ out)
{
    extern __shared__ __align__(128) char smem[];
    const uint32_t sb = smem_u32(smem);
    const int tid = threadIdx.x, wid = tid >> 5, lane = tid & 31;

    if (blockIdx.x < 1152) {
        // =================== QKV PROJECTION ROLE ===================
        // id = ((b*6 + nt)*8 + mloc)*3 + z  -> deps for (b,nt) finish early
        const int id = blockIdx.x;
        const int z    = id % 3;
        const int t3   = id / 3;             // 0..383
        const int mloc = t3 & 7;
        const int t8   = t3 >> 3;            // 0..47
        const int nt   = t8 % 6;
        const int b    = t8 / 6;
        const int m0 = (b * 8 + mloc) * 128, n0 = nt * 128;
        const int wm = wid & 3, wn = wid >> 2;

        const float* A = ((z == 0) ? Q : (z == 1) ? K : V) + (size_t)m0 * DD;
        const __half* B = g_w16[z] + (size_t)n0 * DD;
        const float* bias = (z == 0) ? bq : (z == 1) ? bk : bv;
        __half* oh = (z == 0) ? g_q16 : (z == 1) ? g_k16 : g_v16;
        const float scale = (z == 0) ? 0.125f * LOG2E : 1.0f;

        const int arow[4] = { tid >> 3, (tid + 256) >> 3,
                              (tid + 512) >> 3, (tid + 768) >> 3 };
        const int afsg = tid & 7;

        float4 abuf[4];
        auto ldg_A = [&](int kc) {
            const float* g = A + kc * 32 + afsg * 4;
            #pragma unroll
            for (int t = 0; t < 4; t++)
                abuf[t] = *reinterpret_cast<const float4*>(g + (size_t)arow[t] * DD);
        };
        auto sts_A = [&](int st) {
            char* base = smem + st * STAGE_B;
            #pragma unroll
            for (int t = 0; t < 4; t++) {
                uint2 h;
                h.x = pack_h2(abuf[t].x, abuf[t].y);
                h.y = pack_h2(abuf[t].z, abuf[t].w);
                *reinterpret_cast<uint2*>(base + arow[t] * PH + afsg * 8) = h;
            }
        };
        auto cp_B = [&](int kc, int st) {
            #pragma unroll
            for (int t = 0; t < 2; t++) {
                int iid = tid + t * 256;
                int row = iid >> 2, seg = iid & 3;
                cp_async16(sb + st * STAGE_B + TILE_B + row * PH + seg * 16,
                           B + (size_t)row * DD + kc * 32 + seg * 8);
            }
            cp_commit();
        };

        float acc[2][8][4];
        #pragma unroll
        for (int i = 0; i < 2; i++)
            #pragma unroll
            for (int j = 0; j < 8; j++)
                #pragma unroll
                for (int k = 0; k < 4; k++) acc[i][j][k] = 0.f;

        ldg_A(0);
        cp_B(0, 0);

        const int lrow = lane & 15;
        const int lhalf = lane >> 4;

        #pragma unroll 1
        for (int c = 0; c < NCHUNK; c++) {
            const int s = c & 1;
            sts_A(s);
            if (c + 1 < NCHUNK) {
                ldg_A(c + 1);
                cp_B(c + 1, s ^ 1);
                cp_wait<1>();
            } else {
                cp_wait<0>();
            }
            __syncthreads();

            const uint32_t stg = sb + s * STAGE_B;
            #pragma unroll
            for (int ks = 0; ks < 2; ks++) {
                const int seg = ks * 2 + lhalf;
                uint32_t ah[2][4];
                #pragma unroll
                for (int mf = 0; mf < 2; mf++) {
                    uint32_t off = (uint32_t)((wm * 32 + mf * 16 + lrow) * PH + seg * 16);
                    ldmatrix_x4(ah[mf][0], ah[mf][1], ah[mf][2], ah[mf][3], stg + off);
                }
                #pragma unroll
                for (int ng = 0; ng < 4; ng++) {
                    uint32_t off = (uint32_t)((wn * 64 + ng * 16 + lrow) * PH + seg * 16);
                    uint32_t b0, b1, b2, b3;
                    ldmatrix_x4(b0, b1, b2, b3, stg + TILE_B + off);
                    #pragma unroll
                    for (int mf = 0; mf < 2; mf++) {
                        mma_f16(acc[mf][2*ng  ], ah[mf], b0, b2);
                        mma_f16(acc[mf][2*ng+1], ah[mf], b1, b3);
                    }
                }
            }
            __syncthreads();
        }

        #pragma unroll
        for (int nf = 0; nf < 8; nf++) {
            const int col = n0 + wn * 64 + nf * 8 + (lane & 3) * 2;
            const float b0 = bias[col], b1 = bias[col + 1];
            #pragma unroll
            for (int mf = 0; mf < 2; mf++) {
                const int r0 = m0 + wm * 32 + mf * 16 + (lane >> 2);
                const float* a = acc[mf][nf];
                #pragma unroll
                for (int half = 0; half < 2; half++) {
                    const int m = r0 + half * 8;
                    uint32_t hp = pack_h2((a[2*half] + b0) * scale,
                                          (a[2*half+1] + b1) * scale);
                    int bb = m >> 10, l = m & 1023;
                    int hh = col >> 6, d = col & 63;
                    size_t idx = (((size_t)(bb * HH + hh) << 10) + l) * DHH + d;
                    *reinterpret_cast<uint32_t*>(oh + idx) = hp;
                }
            }
        }

        __syncthreads();
        if (tid == 0) {
            __threadfence();
            atomicAdd(&g_qkv[(b * 6 + nt) * 3 + z], 1);
        }

    } else if (blockIdx.x < 1920) {
        // =================== ATTENTION ROLE ===================
        const int id = blockIdx.x - 1152;
        const int qt = id & 7, h = (id >> 3) % 12, b = id / 96;
        const int q0 = qt * 128;
        const size_t hb = ((size_t)(b * HH + h)) << 16;

        // Wait for Q/K/V of this (b, head-pair) to be projected.
        if (tid == 0) {
            const int base = (b * 6 + (h >> 1)) * 3;
            while (atomicAdd(&g_qkv[base + 0], 0) < 8 ||
                   atomicAdd(&g_qkv[base + 1], 0) < 8 ||
                   atomicAdd(&g_qkv[base + 2], 0) < 8) __nanosleep(128);
            __threadfence();
        }
        __syncthreads();

        const uint32_t SQ = sb;
        auto stage = [&](int s) { return sb + QTILE_B + (uint32_t)s * 2 * KTILE_B; };

        auto load_q = [&]() {
            const __half* g = g_q16 + hb + (size_t)q0 * 64;
            #pragma unroll
            for (int it = 0; it < 4; it++) {
                int iid = tid + it * 256;
                int row = iid >> 3, seg = iid & 7;
                cp_async16(SQ + row * AROWB + seg * 16, g + (size_t)row * 64 + seg * 8);
            }
            cp_commit();
        };
        auto load_kv = [&](int t, int s) {
            const size_t off = hb + (size_t)t * 64 * 64;
            uint32_t st = stage(s);
            #pragma unroll
            for (int it = 0; it < 2; it++) {
                int iid = tid + it * 256;
                int row = iid >> 3, seg = iid & 7;
                cp_async16(st + row * AROWB + seg * 16,
                           g_k16 + off + (size_t)row * 64 + seg * 8);
                cp_async16(st + KTILE_B + row * AROWB + seg * 16,
                           g_v16 + off + (size_t)row * 64 + seg * 8);
            }
            cp_commit();
        };

        load_q();
        load_kv(0, 0);
        cp_wait<1>();
        __syncthreads();

        const int lr = lane & 15, lh = lane >> 4;
        uint32_t qf[4][4];
        #pragma unroll
        for (int ks = 0; ks < 4; ks++) {
            uint32_t off = (uint32_t)((wid * 16 + lr) * AROWB + ks * 32 + lh * 16);
            ldmatrix_x4(qf[ks][0], qf[ks][1], qf[ks][2], qf[ks][3], SQ + off);
        }

        float mA = -INFINITY, mB = -INFINITY, lA = 0.f, lB = 0.f;
        float o[8][4];
        #pragma unroll
        for (int i = 0; i < 8; i++)
            #pragma unroll
            for (int j = 0; j < 4; j++) o[i][j] = 0.f;

        const unsigned char* flagp = g_mflags + (b * 8 + qt) * 8;

        #pragma unroll 1
        for (int t = 0; t < 16; t++) {
            if (t < 15) { load_kv(t + 1, (t + 1) & 1); cp_wait<1>(); }
            else        { cp_wait<0>(); }
            __syncthreads();
            const uint32_t st = stage(t & 1);

            float s[8][4];
            #pragma unroll
            for (int j = 0; j < 8; j++)
                #pragma unroll
                for (int k = 0; k < 4; k++) s[j][k] = 0.f;

            #pragma unroll
            for (int ks = 0; ks < 4; ks++) {
                #pragma unroll
                for (int ng = 0; ng < 4; ng++) {
                    uint32_t off = (uint32_t)((ng * 16 + lr) * AROWB + ks * 32 + lh * 16);
                    uint32_t k0, k1, k2, k3;
                    ldmatrix_x4(k0, k1, k2, k3, st + off);
                    mma_f16(s[2*ng  ], qf[ks], k0, k2);
                    mma_f16(s[2*ng+1], qf[ks], k1, k3);
                }
            }

            if (flagp[t >> 1]) {
                const uint32_t* mr = g_mbits
                    + ((size_t)(b * LL + q0 + wid * 16 + (lane >> 2))) * (LL / 32) + t * 2;
                uint32_t wA[2], wB[2];
                #pragma unroll
                for (int ww = 0; ww < 2; ww++) { wA[ww] = mr[ww]; wB[ww] = mr[8 * (LL/32) + ww]; }
                #pragma unroll
                for (int j = 0; j < 8; j++) {
                    int bp = (j & 3) * 8 + (lane & 3) * 2;
                    uint32_t a = wA[j >> 2], bw = wB[j >> 2];
                    if ((a  >> bp)      & 1u) s[j][0] = -INFINITY;
                    if ((a  >> (bp+1))  & 1u) s[j][1] = -INFINITY;
                    if ((bw >> bp)      & 1u) s[j][2] = -INFINITY;
                    if ((bw >> (bp+1))  & 1u) s[j][3] = -INFINITY;
                }
            }

            float mxA = -INFINITY, mxB = -INFINITY;
            #pragma unroll
            for (int j = 0; j < 8; j++) {
                mxA = fmaxf(mxA, fmaxf(s[j][0], s[j][1]));
                mxB = fmaxf(mxB, fmaxf(s[j][2], s[j][3]));
            }
            mxA = fmaxf(mxA, __shfl_xor_sync(0xffffffffu, mxA, 1));
            mxA = fmaxf(mxA, __shfl_xor_sync(0xffffffffu, mxA, 2));
            mxB = fmaxf(mxB, __shfl_xor_sync(0xffffffffu, mxB, 1));
            mxB = fmaxf(mxB, __shfl_xor_sync(0xffffffffu, mxB, 2));
            float mnA = fmaxf(mA, mxA), mnB = fmaxf(mB, mxB);
            float aA = (mA == -INFINITY) ? 0.f : exp2f(mA - mnA);
            float aB = (mB == -INFINITY) ? 0.f : exp2f(mB - mnB);
            float subA = (mnA == -INFINITY) ? 0.f : mnA;
            float subB = (mnB == -INFINITY) ? 0.f : mnB;
            float sA = 0.f, sB = 0.f;
            #pragma unroll
            for (int j = 0; j < 8; j++) {
                s[j][0] = exp2f(s[j][0] - subA);
                s[j][1] = exp2f(s[j][1] - subA);
                s[j][2] = exp2f(s[j][2] - subB);
                s[j][3] = exp2f(s[j][3] - subB);
                sA += s[j][0] + s[j][1];
                sB += s[j][2] + s[j][3];
            }
            sA += __shfl_xor_sync(0xffffffffu, sA, 1);
            sA += __shfl_xor_sync(0xffffffffu, sA, 2);
            sB += __shfl_xor_sync(0xffffffffu, sB, 1);
            sB += __shfl_xor_sync(0xffffffffu, sB, 2);
            lA = lA * aA + sA; lB = lB * aB + sB;
            mA = mnA; mB = mnB;
            if (aA != 1.f || aB != 1.f) {
                #pragma unroll
                for (int nf = 0; nf < 8; nf++) {
                    o[nf][0] *= aA; o[nf][1] *= aA;
                    o[nf][2] *= aB; o[nf][3] *= aB;
                }
            }

            #pragma unroll
            for (int ks = 0; ks < 4; ks++) {
                uint32_t ap[4];
                ap[0] = pack_h2(s[2*ks  ][0], s[2*ks  ][1]);
                ap[1] = pack_h2(s[2*ks  ][2], s[2*ks  ][3]);
                ap[2] = pack_h2(s[2*ks+1][0], s[2*ks+1][1]);
                ap[3] = pack_h2(s[2*ks+1][2], s[2*ks+1][3]);
                #pragma unroll
                for (int ng = 0; ng < 4; ng++) {
                    uint32_t voff = (uint32_t)((ks * 16 + lr) * AROWB + ng * 32 + lh * 16);
                    uint32_t v0, v1, v2, v3;
                    ldmatrix_x4_t(v0, v1, v2, v3, st + KTILE_B + voff);
                    mma_f16(o[2*ng  ], ap, v0, v1);
                    mma_f16(o[2*ng+1], ap, v2, v3);
                }
            }
            __syncthreads();
        }

        float iA = (lA > 0.f) ? (1.f / lA) : 0.f;
        float iB = (lB > 0.f) ? (1.f / lB) : 0.f;
        size_t rowA = (size_t)b * LL + q0 + wid * 16 + (lane >> 2);
        size_t rowB = rowA + 8;
        #pragma unroll
        for (int nf = 0; nf < 8; nf++) {
            int col = h * 64 + nf * 8 + (lane & 3) * 2;
            *reinterpret_cast<uint32_t*>(g_c16 + rowA * DD + col)
                = pack_h2(o[nf][0] * iA, o[nf][1] * iA);
            *reinterpret_cast<uint32_t*>(g_c16 + rowB * DD + col)
                = pack_h2(o[nf][2] * iB, o[nf][3] * iB);
        }

        __syncthreads();
        if (tid == 0) {
            __threadfence();
            atomicAdd(&g_sync[b * 8 + qt], 1);
        }
    } else {
        // =================== OUT-PROJECTION ROLE ===================
        const int oid = blockIdx.x - 1920;     // 768 tiles: 128 m x 6 n
        const int mt = oid & 127;
        const int nt = oid >> 7;
        const int wm = wid & 3, wn = wid >> 2;

        const int flag = (mt >> 4) * 8 + ((mt & 15) >> 1);
        if (tid == 0) {
            while (atomicAdd(&g_sync[flag], 0) < HH) __nanosleep(128);
            __threadfence();
        }
        __syncthreads();

        const __half* A = g_c16 + (size_t)mt * 64 * DD;
        const __half* B = g_w16[3] + (size_t)nt * 128 * DD;

        auto load_chunk = [&](int kc, int st) {
            #pragma unroll
            for (int t = 0; t < 3; t++) {
                int iid = tid + t * 256;            // 0..767
                uint32_t dst; const __half* src;
                if (iid < 256) {
                    int row = iid >> 2, seg = iid & 3;
                    dst = sb + st * OSTAGE + row * PH + seg * 16;
                    src = A + (size_t)row * DD + kc * 32 + seg * 8;
                } else {
                    int rem = iid - 256;
                    int row = rem >> 2, seg = rem & 3;
                    dst = sb + st * OSTAGE + OA_TILE + row * PH + seg * 16;
                    src = B + (size_t)row * DD + kc * 32 + seg * 8;
                }
                cp_async16(dst, src);
            }
            cp_commit();
        };

        float acc[8][4];
        #pragma unroll
        for (int j = 0; j < 8; j++)
            #pragma unroll
            for (int k = 0; k < 4; k++) acc[j][k] = 0.f;

        load_chunk(0, 0);

        const int lrow = lane & 15;
        const int lhalf = lane >> 4;

        #pragma unroll 1
        for (int c = 0; c < NCHUNK; c++) {
            const int s = c & 1;
            if (c + 1 < NCHUNK) { load_chunk(c + 1, s ^ 1); cp_wait<1>(); }
            else                { cp_wait<0>(); }
            __syncthreads();

            const uint32_t stg = sb + s * OSTAGE;
            #pragma unroll
            for (int ks = 0; ks < 2; ks++) {
                const int seg = ks * 2 + lhalf;
                uint32_t ah[4];
                uint32_t aoff = (uint32_t)((wm * 16 + lrow) * PH + seg * 16);
                ldmatrix_x4(ah[0], ah[1], ah[2], ah[3], stg + aoff);
                #pragma unroll
                for (int ng = 0; ng < 4; ng++) {
                    uint32_t boff = (uint32_t)((wn * 64 + ng * 16 + lrow) * PH + seg * 16);
                    uint32_t b0, b1, b2, b3;
                    ldmatrix_x4(b0, b1, b2, b3, stg + OA_TILE + boff);
                    mma_f16(acc[2*ng  ], ah, b0, b2);
                    mma_f16(acc[2*ng+1], ah, b1, b3);
                }
            }
            __syncthreads();
        }

        #pragma unroll
        for (int nf = 0; nf < 8; nf++) {
            const int col = nt * 128 + wn * 64 + nf * 8 + (lane & 3) * 2;
            const float b0 = bias_o[col], b1 = bias_o[col + 1];
            const int r0 = mt * 64 + wm * 16 + (lane >> 2);
            #pragma unroll
            for (int half = 0; half < 2; half++) {
                const int m = r0 + half * 8;
                *reinterpret_cast<float2*>(out + (size_t)m * DD + col)
                    = make_float2(acc[nf][2*half] + b0, acc[nf][2*half+1] + b1);
            }
        }
    }
}

// ---------------------------------------------------------------------------
extern "C" void kernel_launch(void* const* d_in, const int* in_sizes, int n_in,
                              void* d_out, int out_size)
{
    const float* Query = (const float*)d_in[0];
    const float* Key   = (const float*)d_in[1];
    const float* Value = (const float*)d_in[2];
    const unsigned char* maskp = (const unsigned char*)d_in[3];
    const float* WQ_b = (const float*)d_in[5];
    const float* WK_b = (const float*)d_in[7];
    const float* WV_b = (const float*)d_in[9];
    const float* WO_b = (const float*)d_in[11];
    float* out = (float*)d_out;

    cudaFuncSetAttribute(mha_mega, cudaFuncAttributeMaxDynamicSharedMemorySize,
                         ASMEM);

    // Prep: mask pack/flags + counter reset + weight converts (one launch)
    prep_all<<<2816, 256>>>(maskp,
                            (const float*)d_in[4], (const float*)d_in[6],
                            (const float*)d_in[8], (const float*)d_in[10]);

    // Everything else: one launch
    mha_mega<<<2688, 256, ASMEM>>>(Query, Key, Value,
                                   WQ_b, WK_b, WV_b, WO_b, out);
}